// round 2
// baseline (speedup 1.0000x reference)
#include <cuda_runtime.h>
#include <math.h>

#define NB 32
#define NT 3136
#define DIM 384
#define NH 8
#define CH 48
#define E3 1152
#define EPS 1e-12f

// Scratch (allocation-free rule: __device__ globals)
__device__ float g_q[NB*NH*CH*NT];
__device__ float g_k[NB*NH*CH*NT];
__device__ float g_v[NB*NH*CH*NT];
__device__ float g_o[NB*DIM*NT];          // (B, D, N) layout: d = h*CH + c
__device__ float g_attn[NB*NH*CH*CH];
__device__ float g_qn[NB*NH*CH];
__device__ float g_kn[NB*NH*CH];

// ---------------------------------------------------------------------------
// Kernel 1: QKV GEMM.  Y = x @ qkv_w^T  (M=B*N=100352, Nout=1152, K=384),
// scatter-stored into q/k/v with layout (B,H,C,N).
// ---------------------------------------------------------------------------
__global__ __launch_bounds__(256) void qkv_gemm(const float* __restrict__ x,
                                                const float* __restrict__ w) {
    __shared__ float As[16][68];
    __shared__ float Bs[16][68];
    const int tid   = threadIdx.x;
    const int eBase = blockIdx.x * 64;
    const int b     = blockIdx.y / 49;
    const int nBase = (blockIdx.y % 49) * 64;
    const int mBase = b * NT + nBase;

    const int lr = tid >> 2;          // 0..63
    const int lk = (tid & 3) * 4;     // 0,4,8,12
    const float* xrow = x + (size_t)(mBase + lr) * DIM + lk;
    const float* wrow = w + (size_t)(eBase + lr) * DIM + lk;

    const int n0 = (tid & 15) * 4;    // lanes along n -> coalesced stores
    const int e0 = (tid >> 4) * 4;

    float acc[4][4] = {};

    for (int k0 = 0; k0 < DIM; k0 += 16) {
        float4 av = *(const float4*)(xrow + k0);
        float4 bv = *(const float4*)(wrow + k0);
        As[lk+0][lr] = av.x; As[lk+1][lr] = av.y; As[lk+2][lr] = av.z; As[lk+3][lr] = av.w;
        Bs[lk+0][lr] = bv.x; Bs[lk+1][lr] = bv.y; Bs[lk+2][lr] = bv.z; Bs[lk+3][lr] = bv.w;
        __syncthreads();
        #pragma unroll
        for (int k = 0; k < 16; k++) {
            float4 a  = *(const float4*)&As[k][n0];
            float4 bb = *(const float4*)&Bs[k][e0];
            float ar[4] = {a.x, a.y, a.z, a.w};
            float br[4] = {bb.x, bb.y, bb.z, bb.w};
            #pragma unroll
            for (int i = 0; i < 4; i++)
                #pragma unroll
                for (int j = 0; j < 4; j++)
                    acc[i][j] += ar[i] * br[j];
        }
        __syncthreads();
    }

    #pragma unroll
    for (int j = 0; j < 4; j++) {
        int e = eBase + e0 + j;
        int s = e / DIM;
        int d = e - s * DIM;
        int h = d / CH;
        int c = d - h * CH;
        float* buf = (s == 0) ? g_q : (s == 1) ? g_k : g_v;
        float4 val = make_float4(acc[0][j], acc[1][j], acc[2][j], acc[3][j]);
        *(float4*)(buf + ((size_t)((b * NH + h) * CH + c)) * NT + nBase + n0) = val;
    }
}

// ---------------------------------------------------------------------------
// Kernel 2: L2 norms of q and k over the token axis N, per (b,h,c) row.
// ---------------------------------------------------------------------------
__global__ __launch_bounds__(256) void norms_kernel() {
    const int row = blockIdx.x;                 // 0 .. B*H*C-1
    const float* q = g_q + (size_t)row * NT;
    const float* k = g_k + (size_t)row * NT;
    float sq = 0.f, sk = 0.f;
    for (int i = threadIdx.x * 4; i < NT; i += 256 * 4) {
        float4 a  = *(const float4*)(q + i);
        float4 bb = *(const float4*)(k + i);
        sq += a.x*a.x + a.y*a.y + a.z*a.z + a.w*a.w;
        sk += bb.x*bb.x + bb.y*bb.y + bb.z*bb.z + bb.w*bb.w;
    }
    #pragma unroll
    for (int o = 16; o; o >>= 1) {
        sq += __shfl_xor_sync(0xffffffffu, sq, o);
        sk += __shfl_xor_sync(0xffffffffu, sk, o);
    }
    __shared__ float sQ[8], sK[8];
    const int wid = threadIdx.x >> 5, lane = threadIdx.x & 31;
    if (lane == 0) { sQ[wid] = sq; sK[wid] = sk; }
    __syncthreads();
    if (threadIdx.x == 0) {
        float a = 0.f, bb = 0.f;
        #pragma unroll
        for (int wi = 0; wi < 8; wi++) { a += sQ[wi]; bb += sK[wi]; }
        g_qn[row] = sqrtf(a);
        g_kn[row] = sqrtf(bb);
    }
}

// ---------------------------------------------------------------------------
// Kernel 3: attn = softmax( (Q K^T) / (|q||k|) * temperature ), per (b,h).
// One block per (b,h): 48x48 Gram matrix over N=3136.
// ---------------------------------------------------------------------------
__global__ __launch_bounds__(256) void attn_kernel(const float* __restrict__ temp) {
    __shared__ float qS[48][68];
    __shared__ float kS[48][68];
    __shared__ float S[48][49];
    __shared__ float iqn[48], ikn[48];
    const int bh  = blockIdx.x;
    const int h   = bh & (NH - 1);
    const int tid = threadIdx.x;
    const float* qb = g_q + (size_t)bh * CH * NT;
    const float* kb = g_k + (size_t)bh * CH * NT;

    if (tid < 48) {
        iqn[tid] = 1.f / fmaxf(g_qn[bh * CH + tid], EPS);
        ikn[tid] = 1.f / fmaxf(g_kn[bh * CH + tid], EPS);
    }

    const int c0 = (tid >> 4) * 3;
    const int d0 = (tid & 15) * 3;
    float acc[3][3] = {};

    for (int nb0 = 0; nb0 < NT; nb0 += 64) {
        for (int t = tid; t < 768; t += 256) {
            int r   = t >> 4;
            int col = (t & 15) * 4;
            *(float4*)&qS[r][col] = *(const float4*)(qb + (size_t)r * NT + nb0 + col);
            *(float4*)&kS[r][col] = *(const float4*)(kb + (size_t)r * NT + nb0 + col);
        }
        __syncthreads();
        #pragma unroll
        for (int k = 0; k < 64; k++) {
            float a0 = qS[c0][k], a1 = qS[c0+1][k], a2 = qS[c0+2][k];
            float b0 = kS[d0][k], b1 = kS[d0+1][k], b2 = kS[d0+2][k];
            acc[0][0] += a0*b0; acc[0][1] += a0*b1; acc[0][2] += a0*b2;
            acc[1][0] += a1*b0; acc[1][1] += a1*b1; acc[1][2] += a1*b2;
            acc[2][0] += a2*b0; acc[2][1] += a2*b1; acc[2][2] += a2*b2;
        }
        __syncthreads();
    }

    const float T = temp[h];
    #pragma unroll
    for (int i = 0; i < 3; i++)
        #pragma unroll
        for (int j = 0; j < 3; j++)
            S[c0+i][d0+j] = acc[i][j] * iqn[c0+i] * ikn[d0+j] * T;
    __syncthreads();

    if (tid < 48) {
        float m = -1e30f;
        #pragma unroll 8
        for (int d = 0; d < 48; d++) m = fmaxf(m, S[tid][d]);
        float sum = 0.f;
        #pragma unroll 8
        for (int d = 0; d < 48; d++) { float e = expf(S[tid][d] - m); S[tid][d] = e; sum += e; }
        const float inv = 1.f / sum;
        float* dst = g_attn + (size_t)bh * CH * CH + tid * CH;
        #pragma unroll 8
        for (int d = 0; d < 48; d++) dst[d] = S[tid][d] * inv;
    }
}

// ---------------------------------------------------------------------------
// Kernel 4: out = attn @ v, written as (B, D, N) with d = h*CH + c.
// One block per (b,h, n-tile of 128); each thread owns one token column.
// ---------------------------------------------------------------------------
__global__ __launch_bounds__(128) void av_kernel() {
    __shared__ float aS[48][52];
    const int bh  = blockIdx.y;
    const int nb0 = blockIdx.x * 128;
    const int tid = threadIdx.x;

    const float* ab = g_attn + (size_t)bh * CH * CH;
    for (int t = tid; t < 576; t += 128) {
        int idx = t * 4;
        int r = idx / 48;
        int c = idx - r * 48;
        *(float4*)&aS[r][c] = *(const float4*)(ab + idx);
    }
    __syncthreads();

    const int n = nb0 + tid;
    if (n < NT) {
        const float* vb = g_v + (size_t)bh * CH * NT + n;
        float vreg[48];
        #pragma unroll
        for (int d = 0; d < 48; d++) vreg[d] = vb[(size_t)d * NT];
        const int b = bh >> 3;
        const int h = bh & 7;
        float* ob = g_o + ((size_t)b * DIM + h * CH) * NT + n;
        #pragma unroll 4
        for (int c = 0; c < 48; c++) {
            float s = 0.f;
            #pragma unroll
            for (int d = 0; d < 48; d++) s += aS[c][d] * vreg[d];
            ob[(size_t)c * NT] = s;
        }
    }
}

// ---------------------------------------------------------------------------
// Kernel 5: projection.  y[b,n,e] = sum_d out[b,d,n] * proj_w[e,d] + proj_b[e]
// A is (D, N) per batch (transposed-A GEMM, naturally coalesced along n).
// ---------------------------------------------------------------------------
__global__ __launch_bounds__(256) void proj_gemm(const float* __restrict__ w,
                                                 const float* __restrict__ bias,
                                                 float* __restrict__ y) {
    __shared__ float As[16][68];
    __shared__ float Bs[16][68];
    const int tid   = threadIdx.x;
    const int b     = blockIdx.z;
    const int nBase = blockIdx.y * 64;
    const int eBase = blockIdx.x * 64;
    const float* Ab = g_o + (size_t)b * DIM * NT;

    const int la_k = tid >> 4;          // 0..15
    const int la_n = (tid & 15) * 4;
    const int lb_e = tid >> 2;          // 0..63
    const int lb_k = (tid & 3) * 4;

    const int n0 = (tid >> 4) * 4;
    const int e0 = (tid & 15) * 4;      // lanes along e -> coalesced stores

    float acc[4][4] = {};
    for (int k0 = 0; k0 < DIM; k0 += 16) {
        *(float4*)&As[la_k][la_n] =
            *(const float4*)(Ab + (size_t)(k0 + la_k) * NT + nBase + la_n);
        float4 bv = *(const float4*)(w + (size_t)(eBase + lb_e) * DIM + k0 + lb_k);
        Bs[lb_k+0][lb_e] = bv.x; Bs[lb_k+1][lb_e] = bv.y;
        Bs[lb_k+2][lb_e] = bv.z; Bs[lb_k+3][lb_e] = bv.w;
        __syncthreads();
        #pragma unroll
        for (int k = 0; k < 16; k++) {
            float4 a  = *(const float4*)&As[k][n0];
            float4 bb = *(const float4*)&Bs[k][e0];
            float ar[4] = {a.x, a.y, a.z, a.w};
            float br[4] = {bb.x, bb.y, bb.z, bb.w};
            #pragma unroll
            for (int i = 0; i < 4; i++)
                #pragma unroll
                for (int j = 0; j < 4; j++)
                    acc[i][j] += ar[i] * br[j];
        }
        __syncthreads();
    }

    float4 bsv = *(const float4*)(bias + eBase + e0);
    const float bb4[4] = {bsv.x, bsv.y, bsv.z, bsv.w};
    #pragma unroll
    for (int i = 0; i < 4; i++) {
        float4 val = make_float4(acc[i][0] + bb4[0], acc[i][1] + bb4[1],
                                 acc[i][2] + bb4[2], acc[i][3] + bb4[3]);
        *(float4*)(y + ((size_t)(b * NT + nBase + n0 + i)) * DIM + eBase + e0) = val;
    }
}

// ---------------------------------------------------------------------------
extern "C" void kernel_launch(void* const* d_in, const int* in_sizes, int n_in,
                              void* d_out, int out_size) {
    const float* x      = (const float*)d_in[0];
    const float* qkv_w  = (const float*)d_in[1];
    const float* temp   = (const float*)d_in[2];
    const float* proj_w = (const float*)d_in[3];
    const float* proj_b = (const float*)d_in[4];
    float* y = (float*)d_out;

    qkv_gemm<<<dim3(18, 1568), 256>>>(x, qkv_w);
    norms_kernel<<<NB * NH * CH, 256>>>();
    attn_kernel<<<NB * NH, 256>>>(temp);
    av_kernel<<<dim3(25, NB * NH), 128>>>();
    proj_gemm<<<dim3(6, 49, NB), 256>>>(proj_w, proj_b, y);
}

// round 6
// speedup vs baseline: 2.2910x; 2.2910x over previous
#include <cuda_runtime.h>
#include <cuda_bf16.h>
#include <math.h>
#include <stdint.h>

#define NB 32
#define NT 3136
#define DIM 384
#define NH 8
#define CH 48
#define EPS 1e-12f

// ---------------- scratch (__device__ globals; allocation-free rule) --------
// __align__(256): __device__ arrays only guarantee element alignment, and we
// hit these with 16B cp.async / uint4 / float4 accesses.
__device__ __align__(256) float g_q[NB*NH*CH*NT];
__device__ __align__(256) float g_k[NB*NH*CH*NT];
__device__ __align__(256) float g_v[NB*NH*CH*NT];
__device__ __align__(256) float g_attn[NB*NH*CH*CH];

__device__ __align__(256) __nv_bfloat16 g_xh[(size_t)NB*NT*DIM];
__device__ __align__(256) __nv_bfloat16 g_xl[(size_t)NB*NT*DIM];
__device__ __align__(256) __nv_bfloat16 g_wqh[3*DIM*DIM];
__device__ __align__(256) __nv_bfloat16 g_wql[3*DIM*DIM];
__device__ __align__(256) __nv_bfloat16 g_pwh[DIM*DIM];
__device__ __align__(256) __nv_bfloat16 g_pwl[DIM*DIM];
__device__ __align__(256) __nv_bfloat16 g_oh[(size_t)NB*NT*DIM];  // (b,n,d)
__device__ __align__(256) __nv_bfloat16 g_ol[(size_t)NB*NT*DIM];

// ---------------------------------------------------------------------------
static __device__ __forceinline__ uint32_t sptr(const void* p) {
    return (uint32_t)__cvta_generic_to_shared(p);
}
static __device__ __forceinline__ uint32_t pkbf(__nv_bfloat16 a, __nv_bfloat16 b) {
    uint16_t ua = *reinterpret_cast<uint16_t*>(&a);
    uint16_t ub = *reinterpret_cast<uint16_t*>(&b);
    return (uint32_t)ua | ((uint32_t)ub << 16);
}
static __device__ __forceinline__ void cp16(uint32_t s, const void* g) {
    asm volatile("cp.async.cg.shared.global [%0], [%1], 16;\n" :: "r"(s), "l"(g));
}
static __device__ __forceinline__ void ldsm4(uint32_t* r, uint32_t a) {
    asm volatile("ldmatrix.sync.aligned.m8n8.x4.shared.b16 {%0,%1,%2,%3}, [%4];"
                 : "=r"(r[0]), "=r"(r[1]), "=r"(r[2]), "=r"(r[3]) : "r"(a));
}
static __device__ __forceinline__ void mma16816(float* c, const uint32_t* a,
                                                uint32_t b0, uint32_t b1) {
    asm volatile(
        "mma.sync.aligned.m16n8k16.row.col.f32.bf16.bf16.f32 "
        "{%0,%1,%2,%3}, {%4,%5,%6,%7}, {%8,%9}, {%0,%1,%2,%3};"
        : "+f"(c[0]), "+f"(c[1]), "+f"(c[2]), "+f"(c[3])
        : "r"(a[0]), "r"(a[1]), "r"(a[2]), "r"(a[3]), "r"(b0), "r"(b1));
}

// ---------------------------------------------------------------------------
// Split-convert: fp32 -> (bf16 hi, bf16 lo), 4 elems/thread.
// ---------------------------------------------------------------------------
__global__ __launch_bounds__(256) void conv_split(const float4* __restrict__ src,
                                                  uint2* __restrict__ h,
                                                  uint2* __restrict__ l, int n4) {
    int i = blockIdx.x * 256 + threadIdx.x;
    if (i >= n4) return;
    float4 v = src[i];
    __nv_bfloat16 h0 = __float2bfloat16(v.x), h1 = __float2bfloat16(v.y);
    __nv_bfloat16 h2 = __float2bfloat16(v.z), h3 = __float2bfloat16(v.w);
    __nv_bfloat16 l0 = __float2bfloat16(v.x - __bfloat162float(h0));
    __nv_bfloat16 l1 = __float2bfloat16(v.y - __bfloat162float(h1));
    __nv_bfloat16 l2 = __float2bfloat16(v.z - __bfloat162float(h2));
    __nv_bfloat16 l3 = __float2bfloat16(v.w - __bfloat162float(h3));
    h[i] = make_uint2(pkbf(h0, h1), pkbf(h2, h3));
    l[i] = make_uint2(pkbf(l0, l1), pkbf(l2, l3));
}

// ---------------------------------------------------------------------------
// Tensor-core GEMM, bf16 3-split: C = A(M,384) * B(E,384)^T in ~fp32 accuracy.
// CTA tile 128(m) x 64(e), 8 warps (32x32 each), K-stage 16, cp.async 2-stage.
// MODE 0: scatter to g_q/g_k/g_v (B,H,C,N).  MODE 1: y[m][e] = C + bias.
// ---------------------------------------------------------------------------
template <int MODE>
__global__ __launch_bounds__(256) void gemm_tc(
    const __nv_bfloat16* __restrict__ Ahg, const __nv_bfloat16* __restrict__ Alg,
    const __nv_bfloat16* __restrict__ Bhg, const __nv_bfloat16* __restrict__ Blg,
    const float* __restrict__ bias, float* __restrict__ y) {
    struct Stage {
        __nv_bfloat16 Ah[2][128][24];
        __nv_bfloat16 Al[2][128][24];
        __nv_bfloat16 Bh[2][64][24];
        __nv_bfloat16 Bl[2][64][24];
    };
    // Csm row stride MUST keep float4 accesses 16B-aligned: 68 floats = 272B.
    // (65 was the round-3/4 misaligned-address trap.)
    union Smem { Stage st; float Csm[128][68]; };
    __shared__ __align__(16) Smem sm;

    const int tid   = threadIdx.x;
    const int lane  = tid & 31;
    const int wid   = tid >> 5;
    const int wm    = (wid & 3) * 32;
    const int we    = (wid >> 2) * 32;
    const int mBase = blockIdx.y * 128;
    const int eBase = blockIdx.x * 64;

    // ---- producer (cp.async) addressing: 3 x 16B per thread per stage ----
    const int arow = tid >> 1, achk = (tid & 1) * 8;
    const __nv_bfloat16* gAh = Ahg + (size_t)(mBase + arow) * DIM + achk;
    const __nv_bfloat16* gAl = Alg + (size_t)(mBase + arow) * DIM + achk;
    const int brow = (tid & 127) >> 1;
    const __nv_bfloat16* gB =
        ((tid < 128) ? Bhg : Blg) + (size_t)(eBase + brow) * DIM + achk;
    const uint32_t sAh = sptr(&sm.st.Ah[0][arow][achk]);
    const uint32_t sAl = sptr(&sm.st.Al[0][arow][achk]);
    const uint32_t sB  = (tid < 128) ? sptr(&sm.st.Bh[0][brow][achk])
                                     : sptr(&sm.st.Bl[0][brow][achk]);
    const uint32_t ABUF = 128 * 24 * 2;  // bytes per A stage buffer
    const uint32_t BBUF = 64 * 24 * 2;

    // ---- consumer (ldmatrix) addressing ----
    const int rA  = (lane & 7) + ((lane >> 3) & 1) * 8;
    const int kxA = (lane >> 4) * 8;
    const int rB  = (lane & 7) + (lane >> 4) * 8;
    const int kxB = ((lane >> 3) & 1) * 8;
    const uint32_t aAh = sptr(&sm.st.Ah[0][wm + rA][kxA]);
    const uint32_t aAl = sptr(&sm.st.Al[0][wm + rA][kxA]);
    const uint32_t aBh = sptr(&sm.st.Bh[0][we + rB][kxB]);
    const uint32_t aBl = sptr(&sm.st.Bl[0][we + rB][kxB]);
    const uint32_t TOFF = 16 * 24 * 2;  // 16 rows

    float acc[2][4][4] = {};

    // prologue: stage 0
    cp16(sAh, gAh); cp16(sAl, gAl); cp16(sB, gB);
    asm volatile("cp.async.commit_group;\n");

    const int NS = DIM / 16;  // 24
    for (int s = 0; s < NS; s++) {
        asm volatile("cp.async.wait_group 0;\n");
        __syncthreads();
        if (s + 1 < NS) {
            const int k0 = (s + 1) * 16;
            const uint32_t bo = ((s + 1) & 1);
            cp16(sAh + bo * ABUF, gAh + k0);
            cp16(sAl + bo * ABUF, gAl + k0);
            cp16(sB + bo * BBUF, gB + k0);
        }
        asm volatile("cp.async.commit_group;\n");

        const uint32_t ao = (s & 1) * ABUF;
        const uint32_t bo = (s & 1) * BBUF;
        uint32_t ah[2][4], al[2][4], bh[2][4], bl[2][4];
        ldsm4(ah[0], aAh + ao);        ldsm4(ah[1], aAh + ao + TOFF);
        ldsm4(al[0], aAl + ao);        ldsm4(al[1], aAl + ao + TOFF);
        ldsm4(bh[0], aBh + bo);        ldsm4(bh[1], aBh + bo + TOFF);
        ldsm4(bl[0], aBl + bo);        ldsm4(bl[1], aBl + bo + TOFF);
        #pragma unroll
        for (int im = 0; im < 2; im++)
            #pragma unroll
            for (int jn = 0; jn < 4; jn++) {
                const int ie = jn >> 1, sub = (jn & 1) * 2;
                mma16816(acc[im][jn], ah[im], bh[ie][sub], bh[ie][sub + 1]);
                mma16816(acc[im][jn], al[im], bh[ie][sub], bh[ie][sub + 1]);
                mma16816(acc[im][jn], ah[im], bl[ie][sub], bl[ie][sub + 1]);
            }
    }

    // ---- epilogue: stage C through smem for coalesced stores ----
    __syncthreads();
    const int rr = lane >> 2, cq = (lane & 3) * 2;
    #pragma unroll
    for (int im = 0; im < 2; im++)
        #pragma unroll
        for (int jn = 0; jn < 4; jn++) {
            const int row = wm + im * 16 + rr;
            const int col = we + jn * 8 + cq;
            sm.Csm[row][col]         = acc[im][jn][0];
            sm.Csm[row][col + 1]     = acc[im][jn][1];
            sm.Csm[row + 8][col]     = acc[im][jn][2];
            sm.Csm[row + 8][col + 1] = acc[im][jn][3];
        }
    __syncthreads();

    if (MODE == 0) {
        const int mt = tid & 127, e2 = tid >> 7;
        const int mg = mBase + mt;
        const int b = mg / NT, n = mg - b * NT;
        #pragma unroll 4
        for (int eo = 0; eo < 32; eo++) {
            const int e = eBase + eo * 2 + e2;
            const int sI = e / DIM;
            const int d = e - sI * DIM;
            const int h = d / CH, c = d - h * CH;
            float* buf = (sI == 0) ? g_q : (sI == 1) ? g_k : g_v;
            buf[((size_t)((b * NH + h) * CH + c)) * NT + n] = sm.Csm[mt][eo * 2 + e2];
        }
    } else {
        const int r4 = tid >> 4, c4 = (tid & 15) * 4;
        const float4 bv = *(const float4*)(bias + eBase + c4);
        #pragma unroll
        for (int it = 0; it < 8; it++) {
            const int row = it * 16 + r4;
            float4 v = *(float4*)&sm.Csm[row][c4];
            v.x += bv.x; v.y += bv.y; v.z += bv.z; v.w += bv.w;
            *(float4*)(y + (size_t)(mBase + row) * DIM + eBase + c4) = v;
        }
    }
}

// ---------------------------------------------------------------------------
// attn = softmax( (Q K^T)/(|q||k|) * T ) per (b,h); norms fused into the
// Gram accumulation.
// ---------------------------------------------------------------------------
__global__ __launch_bounds__(256) void attn_kernel(const float* __restrict__ temp) {
    __shared__ float qS[48][68];
    __shared__ float kS[48][68];
    __shared__ float S[48][49];
    __shared__ float iqn[48], ikn[48];
    const int bh  = blockIdx.x;
    const int h   = bh & (NH - 1);
    const int tid = threadIdx.x;
    const float* qb = g_q + (size_t)bh * CH * NT;
    const float* kb = g_k + (size_t)bh * CH * NT;

    const int c0 = (tid >> 4) * 3;
    const int d0 = (tid & 15) * 3;
    const bool doQ = (d0 == 0);
    const bool doK = (c0 == 0);
    float acc[3][3] = {};
    float sq[3] = {}, sk[3] = {};

    for (int nb0 = 0; nb0 < NT; nb0 += 64) {
        for (int t = tid; t < 768; t += 256) {
            int r = t >> 4;
            int col = (t & 15) * 4;
            *(float4*)&qS[r][col] = *(const float4*)(qb + (size_t)r * NT + nb0 + col);
            *(float4*)&kS[r][col] = *(const float4*)(kb + (size_t)r * NT + nb0 + col);
        }
        __syncthreads();
        #pragma unroll
        for (int k = 0; k < 64; k++) {
            float a0 = qS[c0][k], a1 = qS[c0 + 1][k], a2 = qS[c0 + 2][k];
            float b0 = kS[d0][k], b1 = kS[d0 + 1][k], b2 = kS[d0 + 2][k];
            acc[0][0] += a0 * b0; acc[0][1] += a0 * b1; acc[0][2] += a0 * b2;
            acc[1][0] += a1 * b0; acc[1][1] += a1 * b1; acc[1][2] += a1 * b2;
            acc[2][0] += a2 * b0; acc[2][1] += a2 * b1; acc[2][2] += a2 * b2;
            if (doQ) { sq[0] += a0 * a0; sq[1] += a1 * a1; sq[2] += a2 * a2; }
            if (doK) { sk[0] += b0 * b0; sk[1] += b1 * b1; sk[2] += b2 * b2; }
        }
        __syncthreads();
    }

    if (doQ) {
        #pragma unroll
        for (int i = 0; i < 3; i++) iqn[c0 + i] = 1.f / fmaxf(sqrtf(sq[i]), EPS);
    }
    if (doK) {
        #pragma unroll
        for (int i = 0; i < 3; i++) ikn[d0 + i] = 1.f / fmaxf(sqrtf(sk[i]), EPS);
    }
    __syncthreads();

    const float T = temp[h];
    #pragma unroll
    for (int i = 0; i < 3; i++)
        #pragma unroll
        for (int j = 0; j < 3; j++)
            S[c0 + i][d0 + j] = acc[i][j] * iqn[c0 + i] * ikn[d0 + j] * T;
    __syncthreads();

    if (tid < 48) {
        float m = -1e30f;
        #pragma unroll 8
        for (int d = 0; d < 48; d++) m = fmaxf(m, S[tid][d]);
        float sum = 0.f;
        #pragma unroll 8
        for (int d = 0; d < 48; d++) { float e = expf(S[tid][d] - m); S[tid][d] = e; sum += e; }
        const float inv = 1.f / sum;
        float* dst = g_attn + (size_t)bh * CH * CH + tid * CH;
        #pragma unroll 8
        for (int d = 0; d < 48; d++) dst[d] = S[tid][d] * inv;
    }
}

// ---------------------------------------------------------------------------
// out = attn @ v, emitted directly as bf16 hi/lo in (b, n, d) layout so it is
// already the A operand of the proj tensor-core GEMM.
// ---------------------------------------------------------------------------
__global__ __launch_bounds__(128) void av_kernel() {
    __shared__ float aS[48][52];
    const int bh  = blockIdx.y;
    const int nb0 = blockIdx.x * 128;
    const int tid = threadIdx.x;

    const float* ab = g_attn + (size_t)bh * CH * CH;
    for (int t = tid; t < 576; t += 128) {
        int idx = t * 4;
        int r = idx / 48;
        int c = idx - r * 48;
        *(float4*)&aS[r][c] = *(const float4*)(ab + idx);
    }
    __syncthreads();

    const int n = nb0 + tid;
    if (n < NT) {
        const float* vb = g_v + (size_t)bh * CH * NT + n;
        float vreg[48];
        #pragma unroll
        for (int d = 0; d < 48; d++) vreg[d] = vb[(size_t)d * NT];
        float out[48];
        #pragma unroll 4
        for (int c = 0; c < 48; c++) {
            float s = 0.f;
            #pragma unroll
            for (int d = 0; d < 48; d++) s += aS[c][d] * vreg[d];
            out[c] = s;
        }
        const int b = bh >> 3;
        const int h = bh & 7;
        const size_t base = (size_t)(b * NT + n) * DIM + h * CH;
        #pragma unroll
        for (int ch = 0; ch < 6; ch++) {
            uint32_t uh[4], ul[4];
            #pragma unroll
            for (int p = 0; p < 4; p++) {
                float v0 = out[ch * 8 + 2 * p], v1 = out[ch * 8 + 2 * p + 1];
                __nv_bfloat16 h0 = __float2bfloat16(v0);
                __nv_bfloat16 h1 = __float2bfloat16(v1);
                __nv_bfloat16 l0 = __float2bfloat16(v0 - __bfloat162float(h0));
                __nv_bfloat16 l1 = __float2bfloat16(v1 - __bfloat162float(h1));
                uh[p] = pkbf(h0, h1);
                ul[p] = pkbf(l0, l1);
            }
            *(uint4*)(g_oh + base + ch * 8) = make_uint4(uh[0], uh[1], uh[2], uh[3]);
            *(uint4*)(g_ol + base + ch * 8) = make_uint4(ul[0], ul[1], ul[2], ul[3]);
        }
    }
}

// ---------------------------------------------------------------------------
extern "C" void kernel_launch(void* const* d_in, const int* in_sizes, int n_in,
                              void* d_out, int out_size) {
    const float* x      = (const float*)d_in[0];
    const float* qkv_w  = (const float*)d_in[1];
    const float* temp   = (const float*)d_in[2];
    const float* proj_w = (const float*)d_in[3];
    const float* proj_b = (const float*)d_in[4];
    float* y = (float*)d_out;

    __nv_bfloat16 *xh, *xl, *wqh, *wql, *pwh, *pwl, *oh, *ol;
    cudaGetSymbolAddress((void**)&xh, g_xh);
    cudaGetSymbolAddress((void**)&xl, g_xl);
    cudaGetSymbolAddress((void**)&wqh, g_wqh);
    cudaGetSymbolAddress((void**)&wql, g_wql);
    cudaGetSymbolAddress((void**)&pwh, g_pwh);
    cudaGetSymbolAddress((void**)&pwl, g_pwl);
    cudaGetSymbolAddress((void**)&oh, g_oh);
    cudaGetSymbolAddress((void**)&ol, g_ol);

    conv_split<<<37632, 256>>>((const float4*)x, (uint2*)xh, (uint2*)xl,
                               NB * NT * DIM / 4);
    conv_split<<<432, 256>>>((const float4*)qkv_w, (uint2*)wqh, (uint2*)wql,
                             3 * DIM * DIM / 4);
    conv_split<<<144, 256>>>((const float4*)proj_w, (uint2*)pwh, (uint2*)pwl,
                             DIM * DIM / 4);
    gemm_tc<0><<<dim3(18, 784), 256>>>(xh, xl, wqh, wql, nullptr, nullptr);
    attn_kernel<<<NB * NH, 256>>>(temp);
    av_kernel<<<dim3(25, NB * NH), 128>>>();
    gemm_tc<1><<<dim3(6, 784), 256>>>(oh, ol, pwh, pwl, proj_b, y);
}

// round 8
// speedup vs baseline: 2.4375x; 1.0639x over previous
#include <cuda_runtime.h>
#include <cuda_bf16.h>
#include <math.h>
#include <stdint.h>

#define NB 32
#define NT 3136
#define DIM 384
#define NH 8
#define CH 48
#define EPS 1e-12f

// ---------------- scratch (__device__ globals; allocation-free rule) --------
// __align__(256): we hit these with 16B cp.async / float4 / uint2 accesses.
__device__ __align__(256) __nv_bfloat16 g_xh[(size_t)NB*NT*DIM];   // x (b,n,d)
__device__ __align__(256) __nv_bfloat16 g_xl[(size_t)NB*NT*DIM];
__device__ __align__(256) __nv_bfloat16 g_xth[(size_t)NB*DIM*NT];  // x^T (b,d,n)
__device__ __align__(256) __nv_bfloat16 g_xtl[(size_t)NB*DIM*NT];
__device__ __align__(256) __nv_bfloat16 g_wqh[3*DIM*DIM];
__device__ __align__(256) __nv_bfloat16 g_wql[3*DIM*DIM];
__device__ __align__(256) __nv_bfloat16 g_pwh[DIM*DIM];
__device__ __align__(256) __nv_bfloat16 g_pwl[DIM*DIM];
__device__ __align__(256) float g_Gbig[64*DIM*DIM];                // K-split halves
__device__ __align__(256) __nv_bfloat16 g_Gh[NB*DIM*DIM];
__device__ __align__(256) __nv_bfloat16 g_Gl[NB*DIM*DIM];
__device__ __align__(256) float g_tu[(size_t)NB*2*DIM*DIM];        // T(0:384) U(384:768)
__device__ __align__(256) __nv_bfloat16 g_mth[NB*DIM*DIM];         // M^T (b,d',d)
__device__ __align__(256) __nv_bfloat16 g_mtl[NB*DIM*DIM];
__device__ __align__(256) __nv_bfloat16 g_rh[NB*DIM*DIM];          // R (b,e,d')
__device__ __align__(256) __nv_bfloat16 g_rl[NB*DIM*DIM];

// ---------------------------------------------------------------------------
static __device__ __forceinline__ uint32_t sptr(const void* p) {
    return (uint32_t)__cvta_generic_to_shared(p);
}
static __device__ __forceinline__ uint32_t pkbf(__nv_bfloat16 a, __nv_bfloat16 b) {
    uint16_t ua = *reinterpret_cast<uint16_t*>(&a);
    uint16_t ub = *reinterpret_cast<uint16_t*>(&b);
    return (uint32_t)ua | ((uint32_t)ub << 16);
}
static __device__ __forceinline__ void cp16(uint32_t s, const void* g) {
    asm volatile("cp.async.cg.shared.global [%0], [%1], 16;\n" :: "r"(s), "l"(g));
}
static __device__ __forceinline__ void ldsm4(uint32_t* r, uint32_t a) {
    asm volatile("ldmatrix.sync.aligned.m8n8.x4.shared.b16 {%0,%1,%2,%3}, [%4];"
                 : "=r"(r[0]), "=r"(r[1]), "=r"(r[2]), "=r"(r[3]) : "r"(a));
}
static __device__ __forceinline__ void mma16816(float* c, const uint32_t* a,
                                                uint32_t b0, uint32_t b1) {
    asm volatile(
        "mma.sync.aligned.m16n8k16.row.col.f32.bf16.bf16.f32 "
        "{%0,%1,%2,%3}, {%4,%5,%6,%7}, {%8,%9}, {%0,%1,%2,%3};"
        : "+f"(c[0]), "+f"(c[1]), "+f"(c[2]), "+f"(c[3])
        : "r"(a[0]), "r"(a[1]), "r"(a[2]), "r"(a[3]), "r"(b0), "r"(b1));
}
static __device__ __forceinline__ void split1(float v, __nv_bfloat16& h,
                                              __nv_bfloat16& l) {
    h = __float2bfloat16(v);
    l = __float2bfloat16(v - __bfloat162float(h));
}

// ---------------------------------------------------------------------------
// conv_split: fp32 -> (bf16 hi, bf16 lo), 4 elems/thread.
// ---------------------------------------------------------------------------
__global__ __launch_bounds__(256) void conv_split(const float4* __restrict__ src,
                                                  uint2* __restrict__ h,
                                                  uint2* __restrict__ l, int n4) {
    int i = blockIdx.x * 256 + threadIdx.x;
    if (i >= n4) return;
    float4 v = src[i];
    __nv_bfloat16 h0, h1, h2, h3, l0, l1, l2, l3;
    split1(v.x, h0, l0); split1(v.y, h1, l1);
    split1(v.z, h2, l2); split1(v.w, h3, l3);
    h[i] = make_uint2(pkbf(h0, h1), pkbf(h2, h3));
    l[i] = make_uint2(pkbf(l0, l1), pkbf(l2, l3));
}

// sum two G halves and split to bf16 hi/lo
__global__ __launch_bounds__(256) void conv_sum(uint2* __restrict__ h,
                                                uint2* __restrict__ l) {
    const int SLAB4 = DIM * DIM / 4;  // 36864 float4 per slab
    int i = blockIdx.x * 256 + threadIdx.x;
    if (i >= NB * SLAB4) return;
    int b = i / SLAB4, j = i - b * SLAB4;
    const float4* p0 = (const float4*)g_Gbig + (size_t)(2 * b) * SLAB4 + j;
    const float4* p1 = (const float4*)g_Gbig + (size_t)(2 * b + 1) * SLAB4 + j;
    float4 a = *p0, c = *p1;
    float4 v = make_float4(a.x + c.x, a.y + c.y, a.z + c.z, a.w + c.w);
    __nv_bfloat16 h0, h1, h2, h3, l0, l1, l2, l3;
    split1(v.x, h0, l0); split1(v.y, h1, l1);
    split1(v.z, h2, l2); split1(v.w, h3, l3);
    h[i] = make_uint2(pkbf(h0, h1), pkbf(h2, h3));
    l[i] = make_uint2(pkbf(l0, l1), pkbf(l2, l3));
}

// ---------------------------------------------------------------------------
// transpose + split: x (b,n,d) fp32 -> xt hi/lo (b,d,n) bf16
// ---------------------------------------------------------------------------
__global__ __launch_bounds__(256) void transpose_split(const float* __restrict__ x) {
    __shared__ float ts[32][33];
    const int nb = blockIdx.x * 32, db = blockIdx.y * 32, b = blockIdx.z;
    const int tx = threadIdx.x & 31, ty = threadIdx.x >> 5;
    #pragma unroll
    for (int i = 0; i < 4; i++) {
        int n = nb + ty + i * 8;
        ts[ty + i * 8][tx] = x[((size_t)b * NT + n) * DIM + db + tx];
    }
    __syncthreads();
    #pragma unroll
    for (int i = 0; i < 4; i++) {
        int d = db + ty + i * 8;
        float v = ts[tx][ty + i * 8];
        __nv_bfloat16 h, l;
        split1(v, h, l);
        size_t o = ((size_t)b * DIM + d) * NT + nb + tx;
        g_xth[o] = h;
        g_xtl[o] = l;
    }
}

// ---------------------------------------------------------------------------
// Generic HMMA GEMM, bf16 3-split (hh + lh + hl):
//   C(128m x 64n) = A(rows over K) * B(rows over K)^T
// MODE 0: fp32 C -> outF.   MODE 1: split C -> oH/oL.
// MODE 2: y[token, e] = C[e, token] + bias[e]  (transposed store)
// KSPLIT 1: blockIdx.z = 2*batch + khalf (G syrk).
// ---------------------------------------------------------------------------
template <int MODE, int KSPLIT>
__global__ __launch_bounds__(256) void gemm5(
    const __nv_bfloat16* __restrict__ Ahg, const __nv_bfloat16* __restrict__ Alg,
    const __nv_bfloat16* __restrict__ Bhg, const __nv_bfloat16* __restrict__ Blg,
    int lda, int ldb, size_t sA, size_t sB, int NS, int kHalf,
    float* __restrict__ outF, size_t sC, int ldc,
    __nv_bfloat16* __restrict__ oH, __nv_bfloat16* __restrict__ oL,
    const float* __restrict__ bias, float* __restrict__ y) {
    struct Stage {
        __nv_bfloat16 Ah[2][128][24];
        __nv_bfloat16 Al[2][128][24];
        __nv_bfloat16 Bh[2][64][24];
        __nv_bfloat16 Bl[2][64][24];
    };
    union Smem { Stage st; float Csm[128][68]; };
    __shared__ __align__(16) Smem sm;

    const int tid  = threadIdx.x;
    const int lane = tid & 31;
    const int wid  = tid >> 5;
    const int wm   = (wid & 3) * 32;
    const int we   = (wid >> 2) * 32;
    const int mBase = blockIdx.y * 128;
    const int eBase = blockIdx.x * 64;
    const int z  = blockIdx.z;
    const int bz = KSPLIT ? (z >> 1) : z;
    const int koff = KSPLIT ? (z & 1) * kHalf : 0;

    // ---- producer addressing: 3 x cp16 per thread per stage ----
    const int arow = tid >> 1, achk = (tid & 1) * 8;
    const __nv_bfloat16* gAh =
        Ahg + bz * sA + (size_t)(mBase + arow) * lda + koff + achk;
    const __nv_bfloat16* gAl =
        Alg + bz * sA + (size_t)(mBase + arow) * lda + koff + achk;
    const int brow = (tid & 127) >> 1;
    const __nv_bfloat16* gB = ((tid < 128) ? Bhg : Blg) + bz * sB +
                              (size_t)(eBase + brow) * ldb + koff + achk;
    const uint32_t sAh = sptr(&sm.st.Ah[0][arow][achk]);
    const uint32_t sAl = sptr(&sm.st.Al[0][arow][achk]);
    const uint32_t sB_ = (tid < 128) ? sptr(&sm.st.Bh[0][brow][achk])
                                     : sptr(&sm.st.Bl[0][brow][achk]);
    const uint32_t ABUF = 128 * 24 * 2;
    const uint32_t BBUF = 64 * 24 * 2;

    // ---- consumer (ldmatrix) addressing ----
    const int rA  = (lane & 7) + ((lane >> 3) & 1) * 8;
    const int kxA = (lane >> 4) * 8;
    const int rB  = (lane & 7) + (lane >> 4) * 8;
    const int kxB = ((lane >> 3) & 1) * 8;
    const uint32_t aAh = sptr(&sm.st.Ah[0][wm + rA][kxA]);
    const uint32_t aAl = sptr(&sm.st.Al[0][wm + rA][kxA]);
    const uint32_t aBh = sptr(&sm.st.Bh[0][we + rB][kxB]);
    const uint32_t aBl = sptr(&sm.st.Bl[0][we + rB][kxB]);
    const uint32_t TOFF = 16 * 24 * 2;

    float acc[2][4][4] = {};

    cp16(sAh, gAh); cp16(sAl, gAl); cp16(sB_, gB);
    asm volatile("cp.async.commit_group;\n");

    for (int s = 0; s < NS; s++) {
        asm volatile("cp.async.wait_group 0;\n");
        __syncthreads();
        if (s + 1 < NS) {
            const int k0 = (s + 1) * 16;
            const uint32_t bo = ((s + 1) & 1);
            cp16(sAh + bo * ABUF, gAh + k0);
            cp16(sAl + bo * ABUF, gAl + k0);
            cp16(sB_ + bo * BBUF, gB + k0);
        }
        asm volatile("cp.async.commit_group;\n");

        const uint32_t ao = (s & 1) * ABUF;
        const uint32_t bo = (s & 1) * BBUF;
        uint32_t ah[2][4], al[2][4], bh[2][4], bl[2][4];
        ldsm4(ah[0], aAh + ao);        ldsm4(ah[1], aAh + ao + TOFF);
        ldsm4(al[0], aAl + ao);        ldsm4(al[1], aAl + ao + TOFF);
        ldsm4(bh[0], aBh + bo);        ldsm4(bh[1], aBh + bo + TOFF);
        ldsm4(bl[0], aBl + bo);        ldsm4(bl[1], aBl + bo + TOFF);
        #pragma unroll
        for (int im = 0; im < 2; im++)
            #pragma unroll
            for (int jn = 0; jn < 4; jn++) {
                const int ie = jn >> 1, sub = (jn & 1) * 2;
                mma16816(acc[im][jn], ah[im], bh[ie][sub], bh[ie][sub + 1]);
                mma16816(acc[im][jn], al[im], bh[ie][sub], bh[ie][sub + 1]);
                mma16816(acc[im][jn], ah[im], bl[ie][sub], bl[ie][sub + 1]);
            }
    }

    // ---- stage C through smem ----
    __syncthreads();
    const int rr = lane >> 2, cq = (lane & 3) * 2;
    #pragma unroll
    for (int im = 0; im < 2; im++)
        #pragma unroll
        for (int jn = 0; jn < 4; jn++) {
            const int row = wm + im * 16 + rr;
            const int col = we + jn * 8 + cq;
            sm.Csm[row][col]         = acc[im][jn][0];
            sm.Csm[row][col + 1]     = acc[im][jn][1];
            sm.Csm[row + 8][col]     = acc[im][jn][2];
            sm.Csm[row + 8][col + 1] = acc[im][jn][3];
        }
    __syncthreads();

    if (MODE == 0) {
        const int r4 = tid >> 4, c4 = (tid & 15) * 4;
        #pragma unroll
        for (int it = 0; it < 8; it++) {
            const int row = it * 16 + r4;
            *(float4*)(outF + (size_t)z * sC + (size_t)(mBase + row) * ldc +
                       eBase + c4) = *(float4*)&sm.Csm[row][c4];
        }
    } else if (MODE == 1) {
        const int r4 = tid >> 4, c4 = (tid & 15) * 4;
        #pragma unroll
        for (int it = 0; it < 8; it++) {
            const int row = it * 16 + r4;
            float4 v = *(float4*)&sm.Csm[row][c4];
            __nv_bfloat16 h0, h1, h2, h3, l0, l1, l2, l3;
            split1(v.x, h0, l0); split1(v.y, h1, l1);
            split1(v.z, h2, l2); split1(v.w, h3, l3);
            const size_t o = (size_t)z * sC + (size_t)(mBase + row) * ldc +
                             eBase + c4;
            *(uint2*)(oH + o) = make_uint2(pkbf(h0, h1), pkbf(h2, h3));
            *(uint2*)(oL + o) = make_uint2(pkbf(l0, l1), pkbf(l2, l3));
        }
    } else {  // MODE 2: y[token, e] = C[e, n] + bias[e]
        const int e4 = (lane) * 4;        // 0..124 over 32 lanes
        const int nl = wid;               // 0..7
        const float4 bv = *(const float4*)(bias + mBase + e4);
        #pragma unroll
        for (int it = 0; it < 8; it++) {
            const int n = nl + it * 8;
            float4 v = make_float4(sm.Csm[e4][n] + bv.x,
                                   sm.Csm[e4 + 1][n] + bv.y,
                                   sm.Csm[e4 + 2][n] + bv.z,
                                   sm.Csm[e4 + 3][n] + bv.w);
            *(float4*)(y + ((size_t)bz * NT + eBase + n) * DIM + mBase + e4) = v;
        }
    }
}

// ---------------------------------------------------------------------------
// scores: per (b,h) — scores = Wq G Wk^T / (|q||k|) * T, softmax, then
// Mt[d', h*48+c] = sum_{c'} attn[c,c'] * Wv[c', d']  (bf16 hi/lo out).
// Uses T = Wq*G (g_tu rows 0..383) and U = Wk*G (rows 384..767).
// ---------------------------------------------------------------------------
__global__ __launch_bounds__(256) void scores_kernel(
    const float* __restrict__ qkv_w, const float* __restrict__ temp) {
    union {
        struct { float TS[48][36], WkS[48][36], US[48][36], WqS[48][36]; } a;
        float WvS[48][68];
    } __shared__ u;
    __shared__ float Sm[48][49];
    __shared__ float iqn[48], ikn[48];

    const int bh = blockIdx.x, b = bh >> 3, h = bh & 7;
    const int tid = threadIdx.x;
    const float* Tb = g_tu + (size_t)b * 2 * DIM * DIM + (h * CH) * DIM;
    const float* Ub = Tb + (size_t)DIM * DIM;
    const float* Wq = qkv_w + (size_t)(h * CH) * DIM;
    const float* Wk = qkv_w + (size_t)(DIM + h * CH) * DIM;
    const float* Wv = qkv_w + (size_t)(2 * DIM + h * CH) * DIM;

    const int c0 = (tid >> 4) * 3;
    const int d0 = (tid & 15) * 3;
    const bool doQ = (d0 == 0);
    const bool doK = (c0 == 0);
    float acc[3][3] = {};
    float nq[3] = {}, nk[3] = {};

    for (int e0 = 0; e0 < DIM; e0 += 32) {
        for (int t = tid; t < 1536; t += 256) {
            const int arr = t / 384, rem = t - arr * 384;
            const int r = rem >> 3, c4 = (rem & 7) * 4;
            const float4 v = (arr == 0)
                ? *(const float4*)(Tb + (size_t)r * DIM + e0 + c4)
                : (arr == 1)
                ? *(const float4*)(Wk + (size_t)r * DIM + e0 + c4)
                : (arr == 2)
                ? *(const float4*)(Ub + (size_t)r * DIM + e0 + c4)
                : *(const float4*)(Wq + (size_t)r * DIM + e0 + c4);
            float* dst = (arr == 0) ? &u.a.TS[r][c4]
                       : (arr == 1) ? &u.a.WkS[r][c4]
                       : (arr == 2) ? &u.a.US[r][c4]
                                    : &u.a.WqS[r][c4];
            *(float4*)dst = v;
        }
        __syncthreads();
        #pragma unroll
        for (int k = 0; k < 32; k++) {
            float a0 = u.a.TS[c0][k], a1 = u.a.TS[c0+1][k], a2 = u.a.TS[c0+2][k];
            float b0 = u.a.WkS[d0][k], b1 = u.a.WkS[d0+1][k], b2 = u.a.WkS[d0+2][k];
            acc[0][0] += a0*b0; acc[0][1] += a0*b1; acc[0][2] += a0*b2;
            acc[1][0] += a1*b0; acc[1][1] += a1*b1; acc[1][2] += a1*b2;
            acc[2][0] += a2*b0; acc[2][1] += a2*b1; acc[2][2] += a2*b2;
            if (doQ) {
                nq[0] += a0 * u.a.WqS[c0][k];
                nq[1] += a1 * u.a.WqS[c0+1][k];
                nq[2] += a2 * u.a.WqS[c0+2][k];
            }
            if (doK) {
                nk[0] += u.a.US[d0][k] * b0;
                nk[1] += u.a.US[d0+1][k] * b1;
                nk[2] += u.a.US[d0+2][k] * b2;
            }
        }
        __syncthreads();
    }

    if (doQ) {
        #pragma unroll
        for (int i = 0; i < 3; i++) iqn[c0+i] = 1.f / fmaxf(sqrtf(nq[i]), EPS);
    }
    if (doK) {
        #pragma unroll
        for (int i = 0; i < 3; i++) ikn[d0+i] = 1.f / fmaxf(sqrtf(nk[i]), EPS);
    }
    __syncthreads();

    const float T = temp[h];
    #pragma unroll
    for (int i = 0; i < 3; i++)
        #pragma unroll
        for (int j = 0; j < 3; j++)
            Sm[c0+i][d0+j] = acc[i][j] * iqn[c0+i] * ikn[d0+j] * T;
    __syncthreads();

    if (tid < 48) {
        float m = -1e30f;
        #pragma unroll 8
        for (int d = 0; d < 48; d++) m = fmaxf(m, Sm[tid][d]);
        float sum = 0.f;
        #pragma unroll 8
        for (int d = 0; d < 48; d++) { float e = expf(Sm[tid][d] - m); Sm[tid][d] = e; sum += e; }
        const float inv = 1.f / sum;
        #pragma unroll 8
        for (int d = 0; d < 48; d++) Sm[tid][d] *= inv;
    }
    __syncthreads();

    // ---- Phase B: Mt[d', h*48+c] = sum_{c'} Sm[c][c'] * Wv[c'][d'] ----
    const int ci = (tid & 15) * 3;   // 3 c values
    const int dq = (tid >> 4) * 4;   // 4 d' values within 64-chunk
    for (int dp = 0; dp < DIM; dp += 64) {
        for (int t = tid; t < 768; t += 256) {
            const int r = t >> 4, c4 = (t & 15) * 4;
            *(float4*)&u.WvS[r][c4] = *(const float4*)(Wv + (size_t)r * DIM + dp + c4);
        }
        __syncthreads();
        float a4[3][4] = {};
        #pragma unroll 4
        for (int cp = 0; cp < 48; cp++) {
            float s0 = Sm[ci][cp], s1 = Sm[ci+1][cp], s2 = Sm[ci+2][cp];
            float w0 = u.WvS[cp][dq], w1 = u.WvS[cp][dq+1];
            float w2 = u.WvS[cp][dq+2], w3 = u.WvS[cp][dq+3];
            a4[0][0] += s0*w0; a4[0][1] += s0*w1; a4[0][2] += s0*w2; a4[0][3] += s0*w3;
            a4[1][0] += s1*w0; a4[1][1] += s1*w1; a4[1][2] += s1*w2; a4[1][3] += s1*w3;
            a4[2][0] += s2*w0; a4[2][1] += s2*w1; a4[2][2] += s2*w2; a4[2][3] += s2*w3;
        }
        #pragma unroll
        for (int j = 0; j < 4; j++) {
            const size_t rowo = ((size_t)b * DIM + dp + dq + j) * DIM + h * CH + ci;
            #pragma unroll
            for (int i = 0; i < 3; i++) {
                __nv_bfloat16 hh, ll;
                split1(a4[i][j], hh, ll);
                g_mth[rowo + i] = hh;
                g_mtl[rowo + i] = ll;
            }
        }
        __syncthreads();
    }
}

// ---------------------------------------------------------------------------
extern "C" void kernel_launch(void* const* d_in, const int* in_sizes, int n_in,
                              void* d_out, int out_size) {
    const float* x      = (const float*)d_in[0];
    const float* qkv_w  = (const float*)d_in[1];
    const float* temp   = (const float*)d_in[2];
    const float* proj_w = (const float*)d_in[3];
    const float* proj_b = (const float*)d_in[4];
    float* y = (float*)d_out;

    __nv_bfloat16 *xh, *xl, *xth, *xtl, *wqh, *wql, *pwh, *pwl;
    __nv_bfloat16 *Gh, *Gl, *mth, *mtl, *rh, *rl;
    float *Gbig, *tu;
    cudaGetSymbolAddress((void**)&xh, g_xh);
    cudaGetSymbolAddress((void**)&xl, g_xl);
    cudaGetSymbolAddress((void**)&xth, g_xth);
    cudaGetSymbolAddress((void**)&xtl, g_xtl);
    cudaGetSymbolAddress((void**)&wqh, g_wqh);
    cudaGetSymbolAddress((void**)&wql, g_wql);
    cudaGetSymbolAddress((void**)&pwh, g_pwh);
    cudaGetSymbolAddress((void**)&pwl, g_pwl);
    cudaGetSymbolAddress((void**)&Gbig, g_Gbig);
    cudaGetSymbolAddress((void**)&Gh, g_Gh);
    cudaGetSymbolAddress((void**)&Gl, g_Gl);
    cudaGetSymbolAddress((void**)&tu, g_tu);
    cudaGetSymbolAddress((void**)&mth, g_mth);
    cudaGetSymbolAddress((void**)&mtl, g_mtl);
    cudaGetSymbolAddress((void**)&rh, g_rh);
    cudaGetSymbolAddress((void**)&rl, g_rl);

    const size_t sX  = (size_t)NT * DIM;     // per-batch x stride
    const size_t sXT = (size_t)DIM * NT;     // per-batch x^T stride
    const size_t sG  = (size_t)DIM * DIM;

    // converts
    conv_split<<<37632, 256>>>((const float4*)x, (uint2*)xh, (uint2*)xl,
                               NB * NT * DIM / 4);
    transpose_split<<<dim3(NT / 32, DIM / 32, NB), 256>>>(x);
    conv_split<<<432, 256>>>((const float4*)qkv_w, (uint2*)wqh, (uint2*)wql,
                             3 * DIM * DIM / 4);
    conv_split<<<144, 256>>>((const float4*)proj_w, (uint2*)pwh, (uint2*)pwl,
                             DIM * DIM / 4);

    // G = x^T x  (K-split in halves of 1568)
    gemm5<0, 1><<<dim3(6, 3, 64), 256>>>(xth, xtl, xth, xtl,
        NT, NT, sXT, sXT, 98, 1568, Gbig, sG, DIM,
        nullptr, nullptr, nullptr, nullptr);
    conv_sum<<<(NB * DIM * DIM / 4 + 255) / 256, 256>>>((uint2*)Gh, (uint2*)Gl);

    // [T;U] = [Wq;Wk] * G
    gemm5<0, 0><<<dim3(6, 6, 32), 256>>>(wqh, wql, Gh, Gl,
        DIM, DIM, 0, sG, 24, 0, tu, 2 * sG, DIM,
        nullptr, nullptr, nullptr, nullptr);

    // scores + softmax + M^T
    scores_kernel<<<NB * NH, 256>>>(qkv_w, temp);

    // R = P * M  (via B = M^T)
    gemm5<1, 0><<<dim3(6, 3, 32), 256>>>(pwh, pwl, mth, mtl,
        DIM, DIM, 0, sG, 24, 0, nullptr, sG, DIM,
        rh, rl, nullptr, nullptr);

    // y = x R^T + bias  (A = R rows e, B = x rows token; transposed store)
    gemm5<2, 0><<<dim3(49, 3, 32), 256>>>(rh, rl, xh, xl,
        DIM, DIM, sG, sX, 24, 0, nullptr, 0, 0,
        nullptr, nullptr, proj_b, y);
}

// round 11
// speedup vs baseline: 3.9276x; 1.6114x over previous
#include <cuda_runtime.h>
#include <cuda_bf16.h>
#include <math.h>
#include <stdint.h>

#define NB 32
#define NT 3136
#define DIM 384
#define NH 8
#define CH 48
#define EPS 1e-12f

// ---------------- scratch (__device__ globals; allocation-free rule) --------
__device__ __align__(256) __nv_bfloat16 g_xh[(size_t)NB*NT*DIM];   // x (b,n,d)
__device__ __align__(256) __nv_bfloat16 g_xl[(size_t)NB*NT*DIM];
__device__ __align__(256) __nv_bfloat16 g_xth[(size_t)NB*DIM*NT];  // x^T (b,d,n)
__device__ __align__(256) __nv_bfloat16 g_xtl[(size_t)NB*DIM*NT];
__device__ __align__(256) __nv_bfloat16 g_wqh[3*DIM*DIM];
__device__ __align__(256) __nv_bfloat16 g_wql[3*DIM*DIM];
__device__ __align__(256) __nv_bfloat16 g_pwh[DIM*DIM];
__device__ __align__(256) __nv_bfloat16 g_pwl[DIM*DIM];
__device__ __align__(256) float g_Gbig[64*DIM*DIM];                // K-split halves
__device__ __align__(256) __nv_bfloat16 g_Gh[NB*DIM*DIM];
__device__ __align__(256) __nv_bfloat16 g_Gl[NB*DIM*DIM];
__device__ __align__(256) float g_tu[(size_t)NB*2*DIM*DIM];        // T(0:384) U(384:768)
__device__ __align__(256) __nv_bfloat16 g_mth[NB*DIM*DIM];         // M^T (b,d',d)
__device__ __align__(256) __nv_bfloat16 g_mtl[NB*DIM*DIM];
__device__ __align__(256) __nv_bfloat16 g_rh[NB*DIM*DIM];          // R (b,e,d')
__device__ __align__(256) __nv_bfloat16 g_rl[NB*DIM*DIM];

// ---------------------------------------------------------------------------
static __device__ __forceinline__ uint32_t sptr(const void* p) {
    return (uint32_t)__cvta_generic_to_shared(p);
}
static __device__ __forceinline__ uint32_t pkbf(__nv_bfloat16 a, __nv_bfloat16 b) {
    uint16_t ua = *reinterpret_cast<uint16_t*>(&a);
    uint16_t ub = *reinterpret_cast<uint16_t*>(&b);
    return (uint32_t)ua | ((uint32_t)ub << 16);
}
static __device__ __forceinline__ void cp16(uint32_t s, const void* g) {
    asm volatile("cp.async.cg.shared.global [%0], [%1], 16;\n" :: "r"(s), "l"(g));
}
static __device__ __forceinline__ void ldsm4(uint32_t* r, uint32_t a) {
    asm volatile("ldmatrix.sync.aligned.m8n8.x4.shared.b16 {%0,%1,%2,%3}, [%4];"
                 : "=r"(r[0]), "=r"(r[1]), "=r"(r[2]), "=r"(r[3]) : "r"(a));
}
static __device__ __forceinline__ void mma16816(float* c, const uint32_t* a,
                                                uint32_t b0, uint32_t b1) {
    asm volatile(
        "mma.sync.aligned.m16n8k16.row.col.f32.bf16.bf16.f32 "
        "{%0,%1,%2,%3}, {%4,%5,%6,%7}, {%8,%9}, {%0,%1,%2,%3};"
        : "+f"(c[0]), "+f"(c[1]), "+f"(c[2]), "+f"(c[3])
        : "r"(a[0]), "r"(a[1]), "r"(a[2]), "r"(a[3]), "r"(b0), "r"(b1));
}
static __device__ __forceinline__ void split1(float v, __nv_bfloat16& h,
                                              __nv_bfloat16& l) {
    h = __float2bfloat16(v);
    l = __float2bfloat16(v - __bfloat162float(h));
}

// ---------------------------------------------------------------------------
// conv_split: fp32 -> (bf16 hi, bf16 lo), 4 elems/thread.
// ---------------------------------------------------------------------------
__global__ __launch_bounds__(256) void conv_split(const float4* __restrict__ src,
                                                  uint2* __restrict__ h,
                                                  uint2* __restrict__ l, int n4) {
    int i = blockIdx.x * 256 + threadIdx.x;
    if (i >= n4) return;
    float4 v = src[i];
    __nv_bfloat16 h0, h1, h2, h3, l0, l1, l2, l3;
    split1(v.x, h0, l0); split1(v.y, h1, l1);
    split1(v.z, h2, l2); split1(v.w, h3, l3);
    h[i] = make_uint2(pkbf(h0, h1), pkbf(h2, h3));
    l[i] = make_uint2(pkbf(l0, l1), pkbf(l2, l3));
}

// sum two G halves and split to bf16 hi/lo
__global__ __launch_bounds__(256) void conv_sum(uint2* __restrict__ h,
                                                uint2* __restrict__ l) {
    const int SLAB4 = DIM * DIM / 4;
    int i = blockIdx.x * 256 + threadIdx.x;
    if (i >= NB * SLAB4) return;
    int b = i / SLAB4, j = i - b * SLAB4;
    const float4* p0 = (const float4*)g_Gbig + (size_t)(2 * b) * SLAB4 + j;
    const float4* p1 = (const float4*)g_Gbig + (size_t)(2 * b + 1) * SLAB4 + j;
    float4 a = *p0, c = *p1;
    float4 v = make_float4(a.x + c.x, a.y + c.y, a.z + c.z, a.w + c.w);
    __nv_bfloat16 h0, h1, h2, h3, l0, l1, l2, l3;
    split1(v.x, h0, l0); split1(v.y, h1, l1);
    split1(v.z, h2, l2); split1(v.w, h3, l3);
    h[i] = make_uint2(pkbf(h0, h1), pkbf(h2, h3));
    l[i] = make_uint2(pkbf(l0, l1), pkbf(l2, l3));
}

// ---------------------------------------------------------------------------
// Fused: x (b,n,d) fp32 -> x hi/lo (b,n,d) AND x^T hi/lo (b,d,n) bf16.
// Load phase writes the row-layout splits (coalesced along d); store phase
// writes the transposed splits (coalesced along n).
// ---------------------------------------------------------------------------
__global__ __launch_bounds__(256) void transpose_split(const float* __restrict__ x) {
    __shared__ float ts[32][33];
    const int nb = blockIdx.x * 32, db = blockIdx.y * 32, b = blockIdx.z;
    const int tx = threadIdx.x & 31, ty = threadIdx.x >> 5;
    #pragma unroll
    for (int i = 0; i < 4; i++) {
        int n = nb + ty + i * 8;
        float v = x[((size_t)b * NT + n) * DIM + db + tx];
        ts[ty + i * 8][tx] = v;
        __nv_bfloat16 h, l;
        split1(v, h, l);
        size_t o = ((size_t)b * NT + n) * DIM + db + tx;
        g_xh[o] = h;
        g_xl[o] = l;
    }
    __syncthreads();
    #pragma unroll
    for (int i = 0; i < 4; i++) {
        int d = db + ty + i * 8;
        float v = ts[tx][ty + i * 8];
        __nv_bfloat16 h, l;
        split1(v, h, l);
        size_t o = ((size_t)b * DIM + d) * NT + nb + tx;
        g_xth[o] = h;
        g_xtl[o] = l;
    }
}

// ---------------------------------------------------------------------------
// Generic HMMA GEMM, bf16 3-split, 3-stage cp.async ring.
//   C(128m x 64n) = A(rows over K) * B(rows over K)^T
// MODE 0: fp32 C -> outF.   MODE 1: split C -> oH/oL.
// MODE 2: y[token, e] = C[e, token] + bias[e]  (transposed store)
// KSPLIT 1: blockIdx.z = 2*batch + khalf.
// ---------------------------------------------------------------------------
#define STG   18432           // bytes per stage: Ah 6144 | Al 6144 | Bh 3072 | Bl 3072
#define GSMEM (3 * STG)       // 55296; Csm overlay = 128*68*4 = 34816

template <int MODE, int KSPLIT>
__global__ __launch_bounds__(256) void gemm5(
    const __nv_bfloat16* __restrict__ Ahg, const __nv_bfloat16* __restrict__ Alg,
    const __nv_bfloat16* __restrict__ Bhg, const __nv_bfloat16* __restrict__ Blg,
    int lda, int ldb, size_t sA, size_t sB, int NS, int kHalf,
    float* __restrict__ outF, size_t sC, int ldc,
    __nv_bfloat16* __restrict__ oH, __nv_bfloat16* __restrict__ oL,
    const float* __restrict__ bias, float* __restrict__ y) {
    extern __shared__ __align__(16) char dsm[];
    float (*Csm)[68] = (float(*)[68])dsm;
    const uint32_t base = sptr(dsm);

    const int tid  = threadIdx.x;
    const int lane = tid & 31;
    const int wid  = tid >> 5;
    const int wm   = (wid & 3) * 32;
    const int we   = (wid >> 2) * 32;
    const int mBase = blockIdx.y * 128;
    const int eBase = blockIdx.x * 64;
    const int z  = blockIdx.z;
    const int bz = KSPLIT ? (z >> 1) : z;
    const int koff = KSPLIT ? (z & 1) * kHalf : 0;

    // ---- producer addressing (3 x cp16 per thread per stage) ----
    const int arow = tid >> 1, achk = (tid & 1) * 8;
    const __nv_bfloat16* gAh =
        Ahg + bz * sA + (size_t)(mBase + arow) * lda + koff + achk;
    const __nv_bfloat16* gAl =
        Alg + bz * sA + (size_t)(mBase + arow) * lda + koff + achk;
    const int brow = (tid & 127) >> 1;
    const __nv_bfloat16* gB = ((tid < 128) ? Bhg : Blg) + bz * sB +
                              (size_t)(eBase + brow) * ldb + koff + achk;
    const uint32_t sAh = base + (uint32_t)(arow * 48 + (tid & 1) * 16);
    const uint32_t sAl = sAh + 6144;
    const uint32_t sB_ = base + 12288 + ((tid < 128) ? 0u : 3072u) +
                         (uint32_t)(brow * 48 + (tid & 1) * 16);

    // ---- consumer (ldmatrix) addressing ----
    const int rA  = (lane & 7) + ((lane >> 3) & 1) * 8;
    const int kxA = (lane >> 4) * 8;
    const int rB  = (lane & 7) + (lane >> 4) * 8;
    const int kxB = ((lane >> 3) & 1) * 8;
    const uint32_t aAh = base + (uint32_t)((wm + rA) * 48 + kxA * 2);
    const uint32_t aAl = aAh + 6144;
    const uint32_t aBh = base + 12288 + (uint32_t)((we + rB) * 48 + kxB * 2);
    const uint32_t aBl = aBh + 3072;
    const uint32_t TOFF = 768;  // 16 rows * 48B

    float acc[2][4][4] = {};

    auto load_stage = [&](int st, int k0) {
        const uint32_t o = (uint32_t)(st * STG);
        cp16(sAh + o, gAh + k0);
        cp16(sAl + o, gAl + k0);
        cp16(sB_ + o, gB + k0);
    };

    // prologue: stages 0,1 in flight
    load_stage(0, 0);
    asm volatile("cp.async.commit_group;\n");
    load_stage(1, 16);
    asm volatile("cp.async.commit_group;\n");

    int st = 0;
    for (int s = 0; s < NS; s++) {
        asm volatile("cp.async.wait_group 1;\n");  // stage s ready
        __syncthreads();                           // all warps done with s-1
        if (s + 2 < NS) {
            int nst = st + 2; if (nst >= 3) nst -= 3;
            load_stage(nst, (s + 2) * 16);
        }
        asm volatile("cp.async.commit_group;\n");

        const uint32_t o = (uint32_t)(st * STG);
        uint32_t ah[2][4], al[2][4], bh[2][4], bl[2][4];
        ldsm4(ah[0], aAh + o);        ldsm4(ah[1], aAh + o + TOFF);
        ldsm4(al[0], aAl + o);        ldsm4(al[1], aAl + o + TOFF);
        ldsm4(bh[0], aBh + o);        ldsm4(bh[1], aBh + o + TOFF);
        ldsm4(bl[0], aBl + o);        ldsm4(bl[1], aBl + o + TOFF);
        #pragma unroll
        for (int im = 0; im < 2; im++)
            #pragma unroll
            for (int jn = 0; jn < 4; jn++) {
                const int ie = jn >> 1, sub = (jn & 1) * 2;
                mma16816(acc[im][jn], ah[im], bh[ie][sub], bh[ie][sub + 1]);
                mma16816(acc[im][jn], al[im], bh[ie][sub], bh[ie][sub + 1]);
                mma16816(acc[im][jn], ah[im], bl[ie][sub], bl[ie][sub + 1]);
            }
        if (++st == 3) st = 0;
    }

    // ---- stage C through smem (overlays the ring; barrier first) ----
    __syncthreads();
    const int rr = lane >> 2, cq = (lane & 3) * 2;
    #pragma unroll
    for (int im = 0; im < 2; im++)
        #pragma unroll
        for (int jn = 0; jn < 4; jn++) {
            const int row = wm + im * 16 + rr;
            const int col = we + jn * 8 + cq;
            Csm[row][col]         = acc[im][jn][0];
            Csm[row][col + 1]     = acc[im][jn][1];
            Csm[row + 8][col]     = acc[im][jn][2];
            Csm[row + 8][col + 1] = acc[im][jn][3];
        }
    __syncthreads();

    if (MODE == 0) {
        const int r4 = tid >> 4, c4 = (tid & 15) * 4;
        #pragma unroll
        for (int it = 0; it < 8; it++) {
            const int row = it * 16 + r4;
            *(float4*)(outF + (size_t)z * sC + (size_t)(mBase + row) * ldc +
                       eBase + c4) = *(float4*)&Csm[row][c4];
        }
    } else if (MODE == 1) {
        const int r4 = tid >> 4, c4 = (tid & 15) * 4;
        #pragma unroll
        for (int it = 0; it < 8; it++) {
            const int row = it * 16 + r4;
            float4 v = *(float4*)&Csm[row][c4];
            __nv_bfloat16 h0, h1, h2, h3, l0, l1, l2, l3;
            split1(v.x, h0, l0); split1(v.y, h1, l1);
            split1(v.z, h2, l2); split1(v.w, h3, l3);
            const size_t oo = (size_t)z * sC + (size_t)(mBase + row) * ldc +
                              eBase + c4;
            *(uint2*)(oH + oo) = make_uint2(pkbf(h0, h1), pkbf(h2, h3));
            *(uint2*)(oL + oo) = make_uint2(pkbf(l0, l1), pkbf(l2, l3));
        }
    } else {  // MODE 2: y[token, e] = C[e, n] + bias[e]
        const int e4 = lane * 4;
        const int nl = wid;
        const float4 bv = *(const float4*)(bias + mBase + e4);
        #pragma unroll
        for (int it = 0; it < 8; it++) {
            const int n = nl + it * 8;
            float4 v = make_float4(Csm[e4][n] + bv.x,
                                   Csm[e4 + 1][n] + bv.y,
                                   Csm[e4 + 2][n] + bv.z,
                                   Csm[e4 + 3][n] + bv.w);
            *(float4*)(y + ((size_t)bz * NT + eBase + n) * DIM + mBase + e4) = v;
        }
    }
}

// ---------------------------------------------------------------------------
// scores: per (b,h) — scores = Wq G Wk^T / (|q||k|) * T, softmax, then
// Mt[d', h*48+c] = sum_{c'} attn[c,c'] * Wv[c', d']  (bf16 hi/lo out).
// ---------------------------------------------------------------------------
__global__ __launch_bounds__(256) void scores_kernel(
    const float* __restrict__ qkv_w, const float* __restrict__ temp) {
    union {
        struct { float TS[48][36], WkS[48][36], US[48][36], WqS[48][36]; } a;
        float WvS[48][68];
    } __shared__ u;
    __shared__ float Sm[48][49];
    __shared__ float iqn[48], ikn[48];

    const int bh = blockIdx.x, b = bh >> 3, h = bh & 7;
    const int tid = threadIdx.x;
    const float* Tb = g_tu + (size_t)b * 2 * DIM * DIM + (h * CH) * DIM;
    const float* Ub = Tb + (size_t)DIM * DIM;
    const float* Wq = qkv_w + (size_t)(h * CH) * DIM;
    const float* Wk = qkv_w + (size_t)(DIM + h * CH) * DIM;
    const float* Wv = qkv_w + (size_t)(2 * DIM + h * CH) * DIM;

    const int c0 = (tid >> 4) * 3;
    const int d0 = (tid & 15) * 3;
    const bool doQ = (d0 == 0);
    const bool doK = (c0 == 0);
    float acc[3][3] = {};
    float nq[3] = {}, nk[3] = {};

    for (int e0 = 0; e0 < DIM; e0 += 32) {
        for (int t = tid; t < 1536; t += 256) {
            const int arr = t / 384, rem = t - arr * 384;
            const int r = rem >> 3, c4 = (rem & 7) * 4;
            const float4 v = (arr == 0)
                ? *(const float4*)(Tb + (size_t)r * DIM + e0 + c4)
                : (arr == 1)
                ? *(const float4*)(Wk + (size_t)r * DIM + e0 + c4)
                : (arr == 2)
                ? *(const float4*)(Ub + (size_t)r * DIM + e0 + c4)
                : *(const float4*)(Wq + (size_t)r * DIM + e0 + c4);
            float* dst = (arr == 0) ? &u.a.TS[r][c4]
                       : (arr == 1) ? &u.a.WkS[r][c4]
                       : (arr == 2) ? &u.a.US[r][c4]
                                    : &u.a.WqS[r][c4];
            *(float4*)dst = v;
        }
        __syncthreads();
        #pragma unroll
        for (int k = 0; k < 32; k++) {
            float a0 = u.a.TS[c0][k], a1 = u.a.TS[c0+1][k], a2 = u.a.TS[c0+2][k];
            float b0 = u.a.WkS[d0][k], b1 = u.a.WkS[d0+1][k], b2 = u.a.WkS[d0+2][k];
            acc[0][0] += a0*b0; acc[0][1] += a0*b1; acc[0][2] += a0*b2;
            acc[1][0] += a1*b0; acc[1][1] += a1*b1; acc[1][2] += a1*b2;
            acc[2][0] += a2*b0; acc[2][1] += a2*b1; acc[2][2] += a2*b2;
            if (doQ) {
                nq[0] += a0 * u.a.WqS[c0][k];
                nq[1] += a1 * u.a.WqS[c0+1][k];
                nq[2] += a2 * u.a.WqS[c0+2][k];
            }
            if (doK) {
                nk[0] += u.a.US[d0][k] * b0;
                nk[1] += u.a.US[d0+1][k] * b1;
                nk[2] += u.a.US[d0+2][k] * b2;
            }
        }
        __syncthreads();
    }

    if (doQ) {
        #pragma unroll
        for (int i = 0; i < 3; i++) iqn[c0+i] = 1.f / fmaxf(sqrtf(nq[i]), EPS);
    }
    if (doK) {
        #pragma unroll
        for (int i = 0; i < 3; i++) ikn[d0+i] = 1.f / fmaxf(sqrtf(nk[i]), EPS);
    }
    __syncthreads();

    const float T = temp[h];
    #pragma unroll
    for (int i = 0; i < 3; i++)
        #pragma unroll
        for (int j = 0; j < 3; j++)
            Sm[c0+i][d0+j] = acc[i][j] * iqn[c0+i] * ikn[d0+j] * T;
    __syncthreads();

    if (tid < 48) {
        float m = -1e30f;
        #pragma unroll 8
        for (int d = 0; d < 48; d++) m = fmaxf(m, Sm[tid][d]);
        float sum = 0.f;
        #pragma unroll 8
        for (int d = 0; d < 48; d++) { float e = expf(Sm[tid][d] - m); Sm[tid][d] = e; sum += e; }
        const float inv = 1.f / sum;
        #pragma unroll 8
        for (int d = 0; d < 48; d++) Sm[tid][d] *= inv;
    }
    __syncthreads();

    const int ci = (tid & 15) * 3;
    const int dq = (tid >> 4) * 4;
    for (int dp = 0; dp < DIM; dp += 64) {
        for (int t = tid; t < 768; t += 256) {
            const int r = t >> 4, c4 = (t & 15) * 4;
            *(float4*)&u.WvS[r][c4] = *(const float4*)(Wv + (size_t)r * DIM + dp + c4);
        }
        __syncthreads();
        float a4[3][4] = {};
        #pragma unroll 4
        for (int cp = 0; cp < 48; cp++) {
            float s0 = Sm[ci][cp], s1 = Sm[ci+1][cp], s2 = Sm[ci+2][cp];
            float w0 = u.WvS[cp][dq], w1 = u.WvS[cp][dq+1];
            float w2 = u.WvS[cp][dq+2], w3 = u.WvS[cp][dq+3];
            a4[0][0] += s0*w0; a4[0][1] += s0*w1; a4[0][2] += s0*w2; a4[0][3] += s0*w3;
            a4[1][0] += s1*w0; a4[1][1] += s1*w1; a4[1][2] += s1*w2; a4[1][3] += s1*w3;
            a4[2][0] += s2*w0; a4[2][1] += s2*w1; a4[2][2] += s2*w2; a4[2][3] += s2*w3;
        }
        #pragma unroll
        for (int j = 0; j < 4; j++) {
            const size_t rowo = ((size_t)b * DIM + dp + dq + j) * DIM + h * CH + ci;
            #pragma unroll
            for (int i = 0; i < 3; i++) {
                __nv_bfloat16 hh, ll;
                split1(a4[i][j], hh, ll);
                g_mth[rowo + i] = hh;
                g_mtl[rowo + i] = ll;
            }
        }
        __syncthreads();
    }
}

// ---------------------------------------------------------------------------
extern "C" void kernel_launch(void* const* d_in, const int* in_sizes, int n_in,
                              void* d_out, int out_size) {
    const float* x      = (const float*)d_in[0];
    const float* qkv_w  = (const float*)d_in[1];
    const float* temp   = (const float*)d_in[2];
    const float* proj_w = (const float*)d_in[3];
    const float* proj_b = (const float*)d_in[4];
    float* y = (float*)d_out;

    __nv_bfloat16 *xh, *xl, *xth, *xtl, *wqh, *wql, *pwh, *pwl;
    __nv_bfloat16 *Gh, *Gl, *mth, *mtl, *rh, *rl;
    float *Gbig, *tu;
    cudaGetSymbolAddress((void**)&xh, g_xh);
    cudaGetSymbolAddress((void**)&xl, g_xl);
    cudaGetSymbolAddress((void**)&xth, g_xth);
    cudaGetSymbolAddress((void**)&xtl, g_xtl);
    cudaGetSymbolAddress((void**)&wqh, g_wqh);
    cudaGetSymbolAddress((void**)&wql, g_wql);
    cudaGetSymbolAddress((void**)&pwh, g_pwh);
    cudaGetSymbolAddress((void**)&pwl, g_pwl);
    cudaGetSymbolAddress((void**)&Gbig, g_Gbig);
    cudaGetSymbolAddress((void**)&Gh, g_Gh);
    cudaGetSymbolAddress((void**)&Gl, g_Gl);
    cudaGetSymbolAddress((void**)&tu, g_tu);
    cudaGetSymbolAddress((void**)&mth, g_mth);
    cudaGetSymbolAddress((void**)&mtl, g_mtl);
    cudaGetSymbolAddress((void**)&rh, g_rh);
    cudaGetSymbolAddress((void**)&rl, g_rl);

    const size_t sX  = (size_t)NT * DIM;
    const size_t sXT = (size_t)DIM * NT;
    const size_t sG  = (size_t)DIM * DIM;

    cudaFuncSetAttribute(gemm5<0, 1>, cudaFuncAttributeMaxDynamicSharedMemorySize,
                         GSMEM);
    cudaFuncSetAttribute(gemm5<0, 0>, cudaFuncAttributeMaxDynamicSharedMemorySize,
                         GSMEM);
    cudaFuncSetAttribute(gemm5<1, 0>, cudaFuncAttributeMaxDynamicSharedMemorySize,
                         GSMEM);
    cudaFuncSetAttribute(gemm5<2, 0>, cudaFuncAttributeMaxDynamicSharedMemorySize,
                         GSMEM);

    // converts (x hi/lo + x^T hi/lo fused into one pass over x)
    transpose_split<<<dim3(NT / 32, DIM / 32, NB), 256>>>(x);
    conv_split<<<432, 256>>>((const float4*)qkv_w, (uint2*)wqh, (uint2*)wql,
                             3 * DIM * DIM / 4);
    conv_split<<<144, 256>>>((const float4*)proj_w, (uint2*)pwh, (uint2*)pwl,
                             DIM * DIM / 4);

    // G = x^T x  (K-split in halves of 1568)
    gemm5<0, 1><<<dim3(6, 3, 64), 256, GSMEM>>>(xth, xtl, xth, xtl,
        NT, NT, sXT, sXT, 98, 1568, Gbig, sG, DIM,
        nullptr, nullptr, nullptr, nullptr);
    conv_sum<<<(NB * DIM * DIM / 4 + 255) / 256, 256>>>((uint2*)Gh, (uint2*)Gl);

    // [T;U] = [Wq;Wk] * G
    gemm5<0, 0><<<dim3(6, 6, 32), 256, GSMEM>>>(wqh, wql, Gh, Gl,
        DIM, DIM, 0, sG, 24, 0, tu, 2 * sG, DIM,
        nullptr, nullptr, nullptr, nullptr);

    // scores + softmax + M^T
    scores_kernel<<<NB * NH, 256>>>(qkv_w, temp);

    // R = P * M  (via B = M^T)
    gemm5<1, 0><<<dim3(6, 3, 32), 256, GSMEM>>>(pwh, pwl, mth, mtl,
        DIM, DIM, 0, sG, 24, 0, nullptr, sG, DIM,
        rh, rl, nullptr, nullptr);

    // y = x R^T + bias  (A = R rows e, B = x rows token; transposed store)
    gemm5<2, 0><<<dim3(49, 3, 32), 256, GSMEM>>>(rh, rl, xh, xl,
        DIM, DIM, sG, sX, 24, 0, nullptr, 0, 0,
        nullptr, nullptr, proj_b, y);
}

// round 13
// speedup vs baseline: 4.2071x; 1.0712x over previous
#include <cuda_runtime.h>
#include <cuda_bf16.h>
#include <math.h>
#include <stdint.h>

#define NB 32
#define NT 3136
#define DIM 384
#define NH 8
#define CH 48
#define EPS 1e-12f

// ---------------- scratch (__device__ globals; allocation-free rule) --------
// g_xh/g_xl carry 64 extra rows of padding: the final GEMM's 128-wide token
// tiles overrun 3136 (= 24.5 * 128); zero-init padding keeps reads legal.
__device__ __align__(256) __nv_bfloat16 g_xh[(size_t)NB*NT*DIM + 64*DIM];
__device__ __align__(256) __nv_bfloat16 g_xl[(size_t)NB*NT*DIM + 64*DIM];
__device__ __align__(256) __nv_bfloat16 g_xth[(size_t)NB*DIM*NT];  // x^T (b,d,n)
__device__ __align__(256) __nv_bfloat16 g_xtl[(size_t)NB*DIM*NT];
__device__ __align__(256) __nv_bfloat16 g_wqh[3*DIM*DIM];
__device__ __align__(256) __nv_bfloat16 g_wql[3*DIM*DIM];
__device__ __align__(256) __nv_bfloat16 g_pwh[DIM*DIM];
__device__ __align__(256) __nv_bfloat16 g_pwl[DIM*DIM];
__device__ __align__(256) float g_Gbig[64*DIM*DIM];                // K-split halves
__device__ __align__(256) __nv_bfloat16 g_Gh[NB*DIM*DIM];
__device__ __align__(256) __nv_bfloat16 g_Gl[NB*DIM*DIM];
__device__ __align__(256) float g_tu[(size_t)NB*2*DIM*DIM];        // T(0:384) U(384:768)
__device__ __align__(256) __nv_bfloat16 g_mth[NB*DIM*DIM];         // M^T (b,d',d)
__device__ __align__(256) __nv_bfloat16 g_mtl[NB*DIM*DIM];
__device__ __align__(256) __nv_bfloat16 g_rh[NB*DIM*DIM];          // R (b,e,d')
__device__ __align__(256) __nv_bfloat16 g_rl[NB*DIM*DIM];

// ---------------------------------------------------------------------------
static __device__ __forceinline__ uint32_t sptr(const void* p) {
    return (uint32_t)__cvta_generic_to_shared(p);
}
static __device__ __forceinline__ uint32_t pkbf(__nv_bfloat16 a, __nv_bfloat16 b) {
    uint16_t ua = *reinterpret_cast<uint16_t*>(&a);
    uint16_t ub = *reinterpret_cast<uint16_t*>(&b);
    return (uint32_t)ua | ((uint32_t)ub << 16);
}
static __device__ __forceinline__ void cp16(uint32_t s, const void* g) {
    asm volatile("cp.async.cg.shared.global [%0], [%1], 16;\n" :: "r"(s), "l"(g));
}
static __device__ __forceinline__ void ldsm4(uint32_t* r, uint32_t a) {
    asm volatile("ldmatrix.sync.aligned.m8n8.x4.shared.b16 {%0,%1,%2,%3}, [%4];"
                 : "=r"(r[0]), "=r"(r[1]), "=r"(r[2]), "=r"(r[3]) : "r"(a));
}
static __device__ __forceinline__ void mma16816(float* c, const uint32_t* a,
                                                uint32_t b0, uint32_t b1) {
    asm volatile(
        "mma.sync.aligned.m16n8k16.row.col.f32.bf16.bf16.f32 "
        "{%0,%1,%2,%3}, {%4,%5,%6,%7}, {%8,%9}, {%0,%1,%2,%3};"
        : "+f"(c[0]), "+f"(c[1]), "+f"(c[2]), "+f"(c[3])
        : "r"(a[0]), "r"(a[1]), "r"(a[2]), "r"(a[3]), "r"(b0), "r"(b1));
}
static __device__ __forceinline__ void split1(float v, __nv_bfloat16& h,
                                              __nv_bfloat16& l) {
    h = __float2bfloat16(v);
    l = __float2bfloat16(v - __bfloat162float(h));
}

// ---------------------------------------------------------------------------
// conv_split: fp32 -> (bf16 hi, bf16 lo), 4 elems/thread.
// ---------------------------------------------------------------------------
__global__ __launch_bounds__(256) void conv_split(const float4* __restrict__ src,
                                                  uint2* __restrict__ h,
                                                  uint2* __restrict__ l, int n4) {
    int i = blockIdx.x * 256 + threadIdx.x;
    if (i >= n4) return;
    float4 v = src[i];
    __nv_bfloat16 h0, h1, h2, h3, l0, l1, l2, l3;
    split1(v.x, h0, l0); split1(v.y, h1, l1);
    split1(v.z, h2, l2); split1(v.w, h3, l3);
    h[i] = make_uint2(pkbf(h0, h1), pkbf(h2, h3));
    l[i] = make_uint2(pkbf(l0, l1), pkbf(l2, l3));
}

// sum two G halves and split to bf16 hi/lo
__global__ __launch_bounds__(256) void conv_sum(uint2* __restrict__ h,
                                                uint2* __restrict__ l) {
    const int SLAB4 = DIM * DIM / 4;
    int i = blockIdx.x * 256 + threadIdx.x;
    if (i >= NB * SLAB4) return;
    int b = i / SLAB4, j = i - b * SLAB4;
    const float4* p0 = (const float4*)g_Gbig + (size_t)(2 * b) * SLAB4 + j;
    const float4* p1 = (const float4*)g_Gbig + (size_t)(2 * b + 1) * SLAB4 + j;
    float4 a = *p0, c = *p1;
    float4 v = make_float4(a.x + c.x, a.y + c.y, a.z + c.z, a.w + c.w);
    __nv_bfloat16 h0, h1, h2, h3, l0, l1, l2, l3;
    split1(v.x, h0, l0); split1(v.y, h1, l1);
    split1(v.z, h2, l2); split1(v.w, h3, l3);
    h[i] = make_uint2(pkbf(h0, h1), pkbf(h2, h3));
    l[i] = make_uint2(pkbf(l0, l1), pkbf(l2, l3));
}

// ---------------------------------------------------------------------------
// Fused: x (b,n,d) fp32 -> x hi/lo (b,n,d) AND x^T hi/lo (b,d,n) bf16.
// ---------------------------------------------------------------------------
__global__ __launch_bounds__(256) void transpose_split(const float* __restrict__ x) {
    __shared__ float ts[32][33];
    const int nb = blockIdx.x * 32, db = blockIdx.y * 32, b = blockIdx.z;
    const int tx = threadIdx.x & 31, ty = threadIdx.x >> 5;
    #pragma unroll
    for (int i = 0; i < 4; i++) {
        int n = nb + ty + i * 8;
        float v = x[((size_t)b * NT + n) * DIM + db + tx];
        ts[ty + i * 8][tx] = v;
        __nv_bfloat16 h, l;
        split1(v, h, l);
        size_t o = ((size_t)b * NT + n) * DIM + db + tx;
        g_xh[o] = h;
        g_xl[o] = l;
    }
    __syncthreads();
    #pragma unroll
    for (int i = 0; i < 4; i++) {
        int d = db + ty + i * 8;
        float v = ts[tx][ty + i * 8];
        __nv_bfloat16 h, l;
        split1(v, h, l);
        size_t o = ((size_t)b * DIM + d) * NT + nb + tx;
        g_xth[o] = h;
        g_xtl[o] = l;
    }
}

// ---------------------------------------------------------------------------
// HMMA GEMM, bf16 3-split, 3-stage cp.async ring, CTA tile 128m x 128n,
// 8 warps, warp tile 32m x 64n (48 MMA : 12 LDSM per 16-K step).
//   C(128x128) = A(rows over K) * B(rows over K)^T
// MODE 0: fp32 C -> outF.   MODE 1: split C -> oH/oL.
// MODE 2: y[token, e] = C[e, token] + bias[e]  (transposed; token guarded)
// KSPLIT 1: blockIdx.z = 2*batch + khalf.
// ---------------------------------------------------------------------------
#define STG   24576           // per stage: Ah 6144 | Al 6144 | Bh 6144 | Bl 6144
#define GSMEM (3 * STG)       // 73728 >= Csm overlay 128*132*4 = 67584

template <int MODE, int KSPLIT>
__global__ __launch_bounds__(256) void gemm5(
    const __nv_bfloat16* __restrict__ Ahg, const __nv_bfloat16* __restrict__ Alg,
    const __nv_bfloat16* __restrict__ Bhg, const __nv_bfloat16* __restrict__ Blg,
    int lda, int ldb, size_t sA, size_t sB, int NS, int kHalf,
    float* __restrict__ outF, size_t sC, int ldc,
    __nv_bfloat16* __restrict__ oH, __nv_bfloat16* __restrict__ oL,
    const float* __restrict__ bias, float* __restrict__ y) {
    extern __shared__ __align__(16) char dsm[];
    float (*Csm)[132] = (float(*)[132])dsm;
    const uint32_t base = sptr(dsm);

    const int tid  = threadIdx.x;
    const int lane = tid & 31;
    const int wid  = tid >> 5;
    const int wm   = (wid & 3) * 32;
    const int we   = (wid >> 2) * 64;
    const int mBase = blockIdx.y * 128;
    const int eBase = blockIdx.x * 128;
    const int z  = blockIdx.z;
    const int bz = KSPLIT ? (z >> 1) : z;
    const int koff = KSPLIT ? (z & 1) * kHalf : 0;

    // ---- producer addressing (4 x cp16 per thread per stage) ----
    const int arow = tid >> 1, achk = (tid & 1) * 8;
    const __nv_bfloat16* gAh =
        Ahg + bz * sA + (size_t)(mBase + arow) * lda + koff + achk;
    const __nv_bfloat16* gAl =
        Alg + bz * sA + (size_t)(mBase + arow) * lda + koff + achk;
    const __nv_bfloat16* gBh =
        Bhg + bz * sB + (size_t)(eBase + arow) * ldb + koff + achk;
    const __nv_bfloat16* gBl =
        Blg + bz * sB + (size_t)(eBase + arow) * ldb + koff + achk;
    const uint32_t sAh = base + (uint32_t)(arow * 48 + (tid & 1) * 16);

    // ---- consumer (ldmatrix) addressing ----
    const int rA  = (lane & 7) + ((lane >> 3) & 1) * 8;
    const int kxA = (lane >> 4) * 8;
    const int rB  = (lane & 7) + (lane >> 4) * 8;
    const int kxB = ((lane >> 3) & 1) * 8;
    const uint32_t aAh = base + (uint32_t)((wm + rA) * 48 + kxA * 2);
    const uint32_t aAl = aAh + 6144;
    const uint32_t aBh = base + 12288 + (uint32_t)((we + rB) * 48 + kxB * 2);
    const uint32_t aBl = aBh + 6144;
    const uint32_t TOFF = 768;  // 16 rows * 48B

    float acc[2][8][4] = {};

    auto load_stage = [&](int st, int k0) {
        const uint32_t o = (uint32_t)(st * STG);
        cp16(sAh + o, gAh + k0);
        cp16(sAh + o + 6144, gAl + k0);
        cp16(sAh + o + 12288, gBh + k0);
        cp16(sAh + o + 18432, gBl + k0);
    };

    // prologue: stages 0,1 in flight
    load_stage(0, 0);
    asm volatile("cp.async.commit_group;\n");
    load_stage(1, 16);
    asm volatile("cp.async.commit_group;\n");

    int st = 0;
    for (int s = 0; s < NS; s++) {
        asm volatile("cp.async.wait_group 1;\n");  // stage s ready
        __syncthreads();                           // all warps done with s-1
        if (s + 2 < NS) {
            int nst = st + 2; if (nst >= 3) nst -= 3;
            load_stage(nst, (s + 2) * 16);
        }
        asm volatile("cp.async.commit_group;\n");

        const uint32_t o = (uint32_t)(st * STG);
        uint32_t ah[2][4], al[2][4], bh[4][4], bl[4][4];
        ldsm4(ah[0], aAh + o);        ldsm4(ah[1], aAh + o + TOFF);
        ldsm4(al[0], aAl + o);        ldsm4(al[1], aAl + o + TOFF);
        #pragma unroll
        for (int j = 0; j < 4; j++) {
            ldsm4(bh[j], aBh + o + j * TOFF);
            ldsm4(bl[j], aBl + o + j * TOFF);
        }
        #pragma unroll
        for (int im = 0; im < 2; im++)
            #pragma unroll
            for (int jn = 0; jn < 8; jn++) {
                const int ie = jn >> 1, sub = (jn & 1) * 2;
                mma16816(acc[im][jn], ah[im], bh[ie][sub], bh[ie][sub + 1]);
                mma16816(acc[im][jn], al[im], bh[ie][sub], bh[ie][sub + 1]);
                mma16816(acc[im][jn], ah[im], bl[ie][sub], bl[ie][sub + 1]);
            }
        if (++st == 3) st = 0;
    }

    // ---- stage C through smem (overlays the ring; barrier first) ----
    __syncthreads();
    const int rr = lane >> 2, cq = (lane & 3) * 2;
    #pragma unroll
    for (int im = 0; im < 2; im++)
        #pragma unroll
        for (int jn = 0; jn < 8; jn++) {
            const int row = wm + im * 16 + rr;
            const int col = we + jn * 8 + cq;
            if (MODE == 2) {  // transposed: Csm[n][e]
                Csm[col][row]         = acc[im][jn][0];
                Csm[col + 1][row]     = acc[im][jn][1];
                Csm[col][row + 8]     = acc[im][jn][2];
                Csm[col + 1][row + 8] = acc[im][jn][3];
            } else {
                Csm[row][col]         = acc[im][jn][0];
                Csm[row][col + 1]     = acc[im][jn][1];
                Csm[row + 8][col]     = acc[im][jn][2];
                Csm[row + 8][col + 1] = acc[im][jn][3];
            }
        }
    __syncthreads();

    if (MODE == 0) {
        const int r8 = tid >> 5, c4 = (tid & 31) * 4;
        #pragma unroll
        for (int it = 0; it < 16; it++) {
            const int row = it * 8 + r8;
            *(float4*)(outF + (size_t)z * sC + (size_t)(mBase + row) * ldc +
                       eBase + c4) = *(float4*)&Csm[row][c4];
        }
    } else if (MODE == 1) {
        const int r8 = tid >> 5, c4 = (tid & 31) * 4;
        #pragma unroll
        for (int it = 0; it < 16; it++) {
            const int row = it * 8 + r8;
            float4 v = *(float4*)&Csm[row][c4];
            __nv_bfloat16 h0, h1, h2, h3, l0, l1, l2, l3;
            split1(v.x, h0, l0); split1(v.y, h1, l1);
            split1(v.z, h2, l2); split1(v.w, h3, l3);
            const size_t oo = (size_t)z * sC + (size_t)(mBase + row) * ldc +
                              eBase + c4;
            *(uint2*)(oH + oo) = make_uint2(pkbf(h0, h1), pkbf(h2, h3));
            *(uint2*)(oL + oo) = make_uint2(pkbf(l0, l1), pkbf(l2, l3));
        }
    } else {  // MODE 2: y[token, e] = Csm[n][e] + bias[e]
        const int e4 = lane * 4;
        const float4 bv = *(const float4*)(bias + mBase + e4);
        #pragma unroll
        for (int it = 0; it < 16; it++) {
            const int nl = wid + it * 8;
            const int n = eBase + nl;
            if (n < NT) {
                float4 v = *(float4*)&Csm[nl][e4];
                v.x += bv.x; v.y += bv.y; v.z += bv.z; v.w += bv.w;
                *(float4*)(y + ((size_t)bz * NT + n) * DIM + mBase + e4) = v;
            }
        }
    }
}

// ---------------------------------------------------------------------------
// scores: per (b,h) — scores = Wq G Wk^T / (|q||k|) * T, softmax, then
// Mt[d', h*48+c] = sum_{c'} attn[c,c'] * Wv[c', d']  (bf16 hi/lo out).
// ---------------------------------------------------------------------------
__global__ __launch_bounds__(256) void scores_kernel(
    const float* __restrict__ qkv_w, const float* __restrict__ temp) {
    union {
        struct { float TS[48][36], WkS[48][36], US[48][36], WqS[48][36]; } a;
        float WvS[48][68];
    } __shared__ u;
    __shared__ float Sm[48][49];
    __shared__ float iqn[48], ikn[48];

    const int bh = blockIdx.x, b = bh >> 3, h = bh & 7;
    const int tid = threadIdx.x;
    const float* Tb = g_tu + (size_t)b * 2 * DIM * DIM + (h * CH) * DIM;
    const float* Ub = Tb + (size_t)DIM * DIM;
    const float* Wq = qkv_w + (size_t)(h * CH) * DIM;
    const float* Wk = qkv_w + (size_t)(DIM + h * CH) * DIM;
    const float* Wv = qkv_w + (size_t)(2 * DIM + h * CH) * DIM;

    const int c0 = (tid >> 4) * 3;
    const int d0 = (tid & 15) * 3;
    const bool doQ = (d0 == 0);
    const bool doK = (c0 == 0);
    float acc[3][3] = {};
    float nq[3] = {}, nk[3] = {};

    for (int e0 = 0; e0 < DIM; e0 += 32) {
        for (int t = tid; t < 1536; t += 256) {
            const int arr = t / 384, rem = t - arr * 384;
            const int r = rem >> 3, c4 = (rem & 7) * 4;
            const float4 v = (arr == 0)
                ? *(const float4*)(Tb + (size_t)r * DIM + e0 + c4)
                : (arr == 1)
                ? *(const float4*)(Wk + (size_t)r * DIM + e0 + c4)
                : (arr == 2)
                ? *(const float4*)(Ub + (size_t)r * DIM + e0 + c4)
                : *(const float4*)(Wq + (size_t)r * DIM + e0 + c4);
            float* dst = (arr == 0) ? &u.a.TS[r][c4]
                       : (arr == 1) ? &u.a.WkS[r][c4]
                       : (arr == 2) ? &u.a.US[r][c4]
                                    : &u.a.WqS[r][c4];
            *(float4*)dst = v;
        }
        __syncthreads();
        #pragma unroll
        for (int k = 0; k < 32; k++) {
            float a0 = u.a.TS[c0][k], a1 = u.a.TS[c0+1][k], a2 = u.a.TS[c0+2][k];
            float b0 = u.a.WkS[d0][k], b1 = u.a.WkS[d0+1][k], b2 = u.a.WkS[d0+2][k];
            acc[0][0] += a0*b0; acc[0][1] += a0*b1; acc[0][2] += a0*b2;
            acc[1][0] += a1*b0; acc[1][1] += a1*b1; acc[1][2] += a1*b2;
            acc[2][0] += a2*b0; acc[2][1] += a2*b1; acc[2][2] += a2*b2;
            if (doQ) {
                nq[0] += a0 * u.a.WqS[c0][k];
                nq[1] += a1 * u.a.WqS[c0+1][k];
                nq[2] += a2 * u.a.WqS[c0+2][k];
            }
            if (doK) {
                nk[0] += u.a.US[d0][k] * b0;
                nk[1] += u.a.US[d0+1][k] * b1;
                nk[2] += u.a.US[d0+2][k] * b2;
            }
        }
        __syncthreads();
    }

    if (doQ) {
        #pragma unroll
        for (int i = 0; i < 3; i++) iqn[c0+i] = 1.f / fmaxf(sqrtf(nq[i]), EPS);
    }
    if (doK) {
        #pragma unroll
        for (int i = 0; i < 3; i++) ikn[d0+i] = 1.f / fmaxf(sqrtf(nk[i]), EPS);
    }
    __syncthreads();

    const float T = temp[h];
    #pragma unroll
    for (int i = 0; i < 3; i++)
        #pragma unroll
        for (int j = 0; j < 3; j++)
            Sm[c0+i][d0+j] = acc[i][j] * iqn[c0+i] * ikn[d0+j] * T;
    __syncthreads();

    if (tid < 48) {
        float m = -1e30f;
        #pragma unroll 8
        for (int d = 0; d < 48; d++) m = fmaxf(m, Sm[tid][d]);
        float sum = 0.f;
        #pragma unroll 8
        for (int d = 0; d < 48; d++) { float e = expf(Sm[tid][d] - m); Sm[tid][d] = e; sum += e; }
        const float inv = 1.f / sum;
        #pragma unroll 8
        for (int d = 0; d < 48; d++) Sm[tid][d] *= inv;
    }
    __syncthreads();

    const int ci = (tid & 15) * 3;
    const int dq = (tid >> 4) * 4;
    for (int dp = 0; dp < DIM; dp += 64) {
        for (int t = tid; t < 768; t += 256) {
            const int r = t >> 4, c4 = (t & 15) * 4;
            *(float4*)&u.WvS[r][c4] = *(const float4*)(Wv + (size_t)r * DIM + dp + c4);
        }
        __syncthreads();
        float a4[3][4] = {};
        #pragma unroll 4
        for (int cp = 0; cp < 48; cp++) {
            float s0 = Sm[ci][cp], s1 = Sm[ci+1][cp], s2 = Sm[ci+2][cp];
            float w0 = u.WvS[cp][dq], w1 = u.WvS[cp][dq+1];
            float w2 = u.WvS[cp][dq+2], w3 = u.WvS[cp][dq+3];
            a4[0][0] += s0*w0; a4[0][1] += s0*w1; a4[0][2] += s0*w2; a4[0][3] += s0*w3;
            a4[1][0] += s1*w0; a4[1][1] += s1*w1; a4[1][2] += s1*w2; a4[1][3] += s1*w3;
            a4[2][0] += s2*w0; a4[2][1] += s2*w1; a4[2][2] += s2*w2; a4[2][3] += s2*w3;
        }
        #pragma unroll
        for (int j = 0; j < 4; j++) {
            const size_t rowo = ((size_t)b * DIM + dp + dq + j) * DIM + h * CH + ci;
            #pragma unroll
            for (int i = 0; i < 3; i++) {
                __nv_bfloat16 hh, ll;
                split1(a4[i][j], hh, ll);
                g_mth[rowo + i] = hh;
                g_mtl[rowo + i] = ll;
            }
        }
        __syncthreads();
    }
}

// ---------------------------------------------------------------------------
extern "C" void kernel_launch(void* const* d_in, const int* in_sizes, int n_in,
                              void* d_out, int out_size) {
    const float* x      = (const float*)d_in[0];
    const float* qkv_w  = (const float*)d_in[1];
    const float* temp   = (const float*)d_in[2];
    const float* proj_w = (const float*)d_in[3];
    const float* proj_b = (const float*)d_in[4];
    float* y = (float*)d_out;

    __nv_bfloat16 *xh, *xl, *xth, *xtl, *wqh, *wql, *pwh, *pwl;
    __nv_bfloat16 *Gh, *Gl, *mth, *mtl, *rh, *rl;
    float *Gbig, *tu;
    cudaGetSymbolAddress((void**)&xh, g_xh);
    cudaGetSymbolAddress((void**)&xl, g_xl);
    cudaGetSymbolAddress((void**)&xth, g_xth);
    cudaGetSymbolAddress((void**)&xtl, g_xtl);
    cudaGetSymbolAddress((void**)&wqh, g_wqh);
    cudaGetSymbolAddress((void**)&wql, g_wql);
    cudaGetSymbolAddress((void**)&pwh, g_pwh);
    cudaGetSymbolAddress((void**)&pwl, g_pwl);
    cudaGetSymbolAddress((void**)&Gbig, g_Gbig);
    cudaGetSymbolAddress((void**)&Gh, g_Gh);
    cudaGetSymbolAddress((void**)&Gl, g_Gl);
    cudaGetSymbolAddress((void**)&tu, g_tu);
    cudaGetSymbolAddress((void**)&mth, g_mth);
    cudaGetSymbolAddress((void**)&mtl, g_mtl);
    cudaGetSymbolAddress((void**)&rh, g_rh);
    cudaGetSymbolAddress((void**)&rl, g_rl);

    const size_t sX  = (size_t)NT * DIM;
    const size_t sXT = (size_t)DIM * NT;
    const size_t sG  = (size_t)DIM * DIM;

    cudaFuncSetAttribute(gemm5<0, 1>, cudaFuncAttributeMaxDynamicSharedMemorySize,
                         GSMEM);
    cudaFuncSetAttribute(gemm5<0, 0>, cudaFuncAttributeMaxDynamicSharedMemorySize,
                         GSMEM);
    cudaFuncSetAttribute(gemm5<1, 0>, cudaFuncAttributeMaxDynamicSharedMemorySize,
                         GSMEM);
    cudaFuncSetAttribute(gemm5<2, 0>, cudaFuncAttributeMaxDynamicSharedMemorySize,
                         GSMEM);

    // converts (x hi/lo + x^T hi/lo fused into one pass over x)
    transpose_split<<<dim3(NT / 32, DIM / 32, NB), 256>>>(x);
    conv_split<<<432, 256>>>((const float4*)qkv_w, (uint2*)wqh, (uint2*)wql,
                             3 * DIM * DIM / 4);
    conv_split<<<144, 256>>>((const float4*)proj_w, (uint2*)pwh, (uint2*)pwl,
                             DIM * DIM / 4);

    // G = x^T x  (K-split in halves of 1568)
    gemm5<0, 1><<<dim3(3, 3, 64), 256, GSMEM>>>(xth, xtl, xth, xtl,
        NT, NT, sXT, sXT, 98, 1568, Gbig, sG, DIM,
        nullptr, nullptr, nullptr, nullptr);
    conv_sum<<<(NB * DIM * DIM / 4 + 255) / 256, 256>>>((uint2*)Gh, (uint2*)Gl);

    // [T;U] = [Wq;Wk] * G
    gemm5<0, 0><<<dim3(3, 6, 32), 256, GSMEM>>>(wqh, wql, Gh, Gl,
        DIM, DIM, 0, sG, 24, 0, tu, 2 * sG, DIM,
        nullptr, nullptr, nullptr, nullptr);

    // scores + softmax + M^T
    scores_kernel<<<NB * NH, 256>>>(qkv_w, temp);

    // R = P * M  (via B = M^T)
    gemm5<1, 0><<<dim3(3, 3, 32), 256, GSMEM>>>(pwh, pwl, mth, mtl,
        DIM, DIM, 0, sG, 24, 0, nullptr, sG, DIM,
        rh, rl, nullptr, nullptr);

    // y = x R^T + bias  (A = R rows e, B = x rows token; transposed store)
    gemm5<2, 0><<<dim3(25, 3, 32), 256, GSMEM>>>(rh, rl, xh, xl,
        DIM, DIM, sG, sX, 24, 0, nullptr, 0, 0,
        nullptr, nullptr, proj_b, y);
}